// round 1
// baseline (speedup 1.0000x reference)
#include <cuda_runtime.h>
#include <cstdint>

#define B_ 8
#define S_ 2048
#define D_ 1024
#define H_ 64
#define M_ (B_*S_)      // 16384 rows
#define PAD 68          // smem row stride (floats): 16B-aligned, conflict-free patterns

typedef unsigned long long u64;

// ---------- packed fp32x2 helpers (sm_100+ PTX) ----------
__device__ __forceinline__ u64 pack2(float a, float b) {
    u64 r; asm("mov.b64 %0,{%1,%2};" : "=l"(r) : "f"(a), "f"(b)); return r;
}
__device__ __forceinline__ float2 unpack2(u64 v) {
    float2 r; asm("mov.b64 {%0,%1},%2;" : "=f"(r.x), "=f"(r.y) : "l"(v)); return r;
}
__device__ __forceinline__ void fma2(u64& acc, u64 a, u64 b) {
    asm("fma.rn.f32x2 %0,%1,%2,%0;" : "+l"(acc) : "l"(a), "l"(b));
}
__device__ __forceinline__ u64 mul2(u64 a, u64 b) {
    u64 r; asm("mul.rn.f32x2 %0,%1,%2;" : "=l"(r) : "l"(a), "l"(b)); return r;
}

// ---------- scratch for projections (no cudaMalloc allowed) ----------
__device__ float g_q[(size_t)M_ * H_];
__device__ float g_k[(size_t)M_ * H_];
__device__ float g_v[(size_t)M_ * H_];

// ============================================================================
// Kernel 1: fused QKV projection.
// x[16384,1024] @ {Wk,Wq,Wv}[1024,64] -> g_k, g_q, g_v [16384,64].
// Block: 256 threads, BM=64 rows, BN=192 (all three heads), BK=16.
// Each x row is read from DRAM exactly once. W tiles stream from L2.
// Thread tile: 8 rows (stride 8) x 3 col-pairs (f32x2) = 48 fp32 outputs.
// ============================================================================
__global__ __launch_bounds__(256) void qkv_kernel(
    const float* __restrict__ x,
    const float* __restrict__ Wk, const float* __restrict__ Wq, const float* __restrict__ Wv)
{
    __shared__ float xs[64][16];
    __shared__ float ws[16][196];   // 196 = 192 + 4 pad (bank-shift rows, keeps 16B align)

    const int tid = threadIdx.x;
    const int ty  = tid >> 5;       // 0..7  (warp id; rows ty, ty+8, ..., ty+56)
    const int tx  = tid & 31;       // 0..31 (col pair 2*tx within each 64-wide head)
    const int r0  = blockIdx.x * 64;

    const int lr = tid >> 2, lc = (tid & 3) * 4;     // x tile load map
    const int wk = tid >> 4, wn = (tid & 15) * 4;    // W tile load map

    u64 acc[8][3];
    #pragma unroll
    for (int i = 0; i < 8; i++)
        #pragma unroll
        for (int j = 0; j < 3; j++) acc[i][j] = 0ull;

    for (int k0 = 0; k0 < D_; k0 += 16) {
        __syncthreads();
        *(float4*)&xs[lr][lc]     = *(const float4*)&x [(size_t)(r0 + lr) * D_ + k0 + lc];
        *(float4*)&ws[wk][wn]     = *(const float4*)&Wk[(size_t)(k0 + wk) * H_ + wn];
        *(float4*)&ws[wk][64+wn]  = *(const float4*)&Wq[(size_t)(k0 + wk) * H_ + wn];
        *(float4*)&ws[wk][128+wn] = *(const float4*)&Wv[(size_t)(k0 + wk) * H_ + wn];
        __syncthreads();

        #pragma unroll
        for (int kk = 0; kk < 16; kk++) {
            u64 aa[8];
            #pragma unroll
            for (int i = 0; i < 8; i++) {
                float a = xs[ty + i * 8][kk];        // broadcast within warp
                aa[i] = pack2(a, a);
            }
            u64 b0 = *(const u64*)&ws[kk][      tx * 2];
            u64 b1 = *(const u64*)&ws[kk][ 64 + tx * 2];
            u64 b2 = *(const u64*)&ws[kk][128 + tx * 2];
            #pragma unroll
            for (int i = 0; i < 8; i++) {
                fma2(acc[i][0], aa[i], b0);
                fma2(acc[i][1], aa[i], b1);
                fma2(acc[i][2], aa[i], b2);
            }
        }
    }

    #pragma unroll
    for (int i = 0; i < 8; i++) {
        size_t row = (size_t)(r0 + ty + i * 8);
        float2 fk = unpack2(acc[i][0]);
        float2 fq = unpack2(acc[i][1]);
        float2 fv = unpack2(acc[i][2]);
        *(float2*)&g_k[row * H_ + tx * 2] = fk;
        *(float2*)&g_q[row * H_ + tx * 2] = fq;
        *(float2*)&g_v[row * H_ + tx * 2] = fv;
    }
}

// ============================================================================
// Kernel 2: flash attention (fp32, f32x2 inner loops).
// Grid (32 q-tiles, 8 batches), 256 threads. Tiles 64x64, head dim 64.
// A (row-major, stride PAD) x Bt (d-major, stride PAD) -> acc[4 q][2 f32x2 pairs]
// Thread map: tx=0..15 owns 4 consecutive output cols (4*tx..), ty=0..15 owns
// 4 consecutive rows (4*ty..). All smem reads broadcast or conflict-free.
// ============================================================================
__device__ __forceinline__ void tile_mm(
    const float* __restrict__ A, const float* __restrict__ Bt,
    int ty4, int tx, u64 acc[4][2])
{
    #pragma unroll 4
    for (int d0 = 0; d0 < 64; d0 += 4) {
        float4 a4[4];
        #pragma unroll
        for (int qi = 0; qi < 4; qi++)
            a4[qi] = *(const float4*)&A[(ty4 + qi) * PAD + d0];
        #pragma unroll
        for (int dd = 0; dd < 4; dd++) {
            ulonglong2 bb = *(const ulonglong2*)&Bt[(d0 + dd) * PAD + tx * 4];
            #pragma unroll
            for (int qi = 0; qi < 4; qi++) {
                float a = (dd == 0) ? a4[qi].x : (dd == 1) ? a4[qi].y
                        : (dd == 2) ? a4[qi].z : a4[qi].w;
                u64 aa = pack2(a, a);
                fma2(acc[qi][0], aa, bb.x);
                fma2(acc[qi][1], aa, bb.y);
            }
        }
    }
}

__global__ __launch_bounds__(256) void attn_kernel(float* __restrict__ Out)
{
    extern __shared__ float sm[];
    float* Qs  = sm;                 // [64][PAD] q-major, pre-scaled by D^-0.5
    float* Ks  = Qs + 64 * PAD;      // [64][PAD] d-major (transposed on load)
    float* Vs  = Ks + 64 * PAD;      // [64][PAD] k-major
    float* Ss  = Vs + 64 * PAD;      // [64][PAD] scores -> probabilities
    float* m_s  = Ss + 64 * PAD;     // running row max
    float* l_s  = m_s + 64;          // running row sum
    float* al_s = l_s + 64;          // per-tile correction factor

    const int tid = threadIdx.x;
    const int tx  = tid & 15;
    const int ty  = tid >> 4;
    const int ty4 = ty * 4;
    const int qt  = blockIdx.x;
    const int b   = blockIdx.y;

    const float* Qb = g_q + ((size_t)b * S_ + (size_t)qt * 64) * H_;
    const float* Kb = g_k + (size_t)b * S_ * H_;
    const float* Vb = g_v + (size_t)b * S_ * H_;

    const float scale = 0.03125f;   // 1024^-0.5 (reference uses embedding dim!)
    for (int i = tid; i < 64 * 16; i += 256) {
        int r = i >> 4, c = (i & 15) * 4;
        float4 f = *(const float4*)&Qb[(size_t)r * H_ + c];
        f.x *= scale; f.y *= scale; f.z *= scale; f.w *= scale;
        *(float4*)&Qs[r * PAD + c] = f;
    }
    if (tid < 64) { m_s[tid] = -1e30f; l_s[tid] = 0.f; }

    u64 o2[4][2];
    #pragma unroll
    for (int qi = 0; qi < 4; qi++) { o2[qi][0] = 0ull; o2[qi][1] = 0ull; }

    for (int kt = 0; kt <= qt; kt++) {
        __syncthreads();   // prev phase C done before overwriting Ks/Vs/Ss
        const float* Kt = Kb + (size_t)kt * 64 * H_;
        const float* Vt = Vb + (size_t)kt * 64 * H_;
        for (int i = tid; i < 64 * 16; i += 256) {
            int r = i >> 4, c = (i & 15) * 4;
            float4 fk = *(const float4*)&Kt[(size_t)r * H_ + c];
            Ks[(c + 0) * PAD + r] = fk.x;     // transpose K -> d-major
            Ks[(c + 1) * PAD + r] = fk.y;
            Ks[(c + 2) * PAD + r] = fk.z;
            Ks[(c + 3) * PAD + r] = fk.w;
            *(float4*)&Vs[r * PAD + c] = *(const float4*)&Vt[(size_t)r * H_ + c];
        }
        __syncthreads();

        // ---- phase A: S = Q K^T (scale folded into Q) ----
        u64 s2[4][2];
        #pragma unroll
        for (int qi = 0; qi < 4; qi++) { s2[qi][0] = 0ull; s2[qi][1] = 0ull; }
        tile_mm(Qs, Ks, ty4, tx, s2);

        const bool diag = (kt == qt);
        #pragma unroll
        for (int qi = 0; qi < 4; qi++) {
            float2 p0 = unpack2(s2[qi][0]);   // k cols 4tx+0, 4tx+1
            float2 p1 = unpack2(s2[qi][1]);   // k cols 4tx+2, 4tx+3
            if (diag) {
                int qg = ty4 + qi, kg = tx * 4;
                if (kg + 0 > qg) p0.x = -1e30f;
                if (kg + 1 > qg) p0.y = -1e30f;
                if (kg + 2 > qg) p1.x = -1e30f;
                if (kg + 3 > qg) p1.y = -1e30f;
            }
            float4 f = make_float4(p0.x, p0.y, p1.x, p1.y);
            *(float4*)&Ss[(ty4 + qi) * PAD + tx * 4] = f;
        }
        __syncthreads();

        // ---- phase B: online softmax, one thread per query row ----
        if (tid < 64) {
            float* row = Ss + tid * PAD;
            float mp = m_s[tid];
            float mm = mp;
            #pragma unroll
            for (int i = 0; i < 16; i++) {
                float4 f = *(const float4*)&row[i * 4];
                mm = fmaxf(mm, fmaxf(fmaxf(f.x, f.y), fmaxf(f.z, f.w)));
            }
            float alpha = __expf(mp - mm);
            float ls = 0.f;
            #pragma unroll
            for (int i = 0; i < 16; i++) {
                float4 f = *(float4*)&row[i * 4];
                f.x = __expf(f.x - mm); f.y = __expf(f.y - mm);
                f.z = __expf(f.z - mm); f.w = __expf(f.w - mm);
                ls += f.x + f.y + f.z + f.w;
                *(float4*)&row[i * 4] = f;
            }
            m_s[tid]  = mm;
            l_s[tid]  = l_s[tid] * alpha + ls;
            al_s[tid] = alpha;
        }
        __syncthreads();

        // ---- phase C: O = O*alpha + P V ----
        #pragma unroll
        for (int qi = 0; qi < 4; qi++) {
            float av = al_s[ty4 + qi];
            u64 aa = pack2(av, av);
            o2[qi][0] = mul2(o2[qi][0], aa);
            o2[qi][1] = mul2(o2[qi][1], aa);
        }
        tile_mm(Ss, Vs, ty4, tx, o2);
    }

    // normalize and write
    #pragma unroll
    for (int qi = 0; qi < 4; qi++) {
        float inv = 1.0f / l_s[ty4 + qi];
        float2 p0 = unpack2(o2[qi][0]);
        float2 p1 = unpack2(o2[qi][1]);
        float4 f = make_float4(p0.x * inv, p0.y * inv, p1.x * inv, p1.y * inv);
        size_t row = (size_t)b * S_ + (size_t)qt * 64 + ty4 + qi;
        *(float4*)&Out[row * H_ + tx * 4] = f;
    }
}

// ============================================================================
extern "C" void kernel_launch(void* const* d_in, const int* in_sizes, int n_in,
                              void* d_out, int out_size)
{
    const float* x  = (const float*)d_in[0];
    const float* Wk = (const float*)d_in[1];
    const float* Wq = (const float*)d_in[2];
    const float* Wv = (const float*)d_in[3];
    float* out = (float*)d_out;

    qkv_kernel<<<M_ / 64, 256>>>(x, Wk, Wq, Wv);

    const int smem_bytes = (4 * 64 * PAD + 3 * 64) * sizeof(float);  // 70400 B
    cudaFuncSetAttribute(attn_kernel, cudaFuncAttributeMaxDynamicSharedMemorySize, smem_bytes);
    dim3 grid(S_ / 64, B_);
    attn_kernel<<<grid, 256, smem_bytes>>>(out);
}

// round 4
// speedup vs baseline: 1.1787x; 1.1787x over previous
#include <cuda_runtime.h>
#include <cstdint>

#define B_ 8
#define S_ 2048
#define D_ 1024
#define H_ 64
#define M_ (B_*S_)      // 16384 rows

typedef unsigned long long u64;
typedef unsigned int u32;

// ---------- packed fp32x2 helpers ----------
__device__ __forceinline__ u64 pack2(float a, float b) {
    u64 r; asm("mov.b64 %0,{%1,%2};" : "=l"(r) : "f"(a), "f"(b)); return r;
}
__device__ __forceinline__ float2 unpack2(u64 v) {
    float2 r; asm("mov.b64 {%0,%1},%2;" : "=f"(r.x), "=f"(r.y) : "l"(v)); return r;
}
__device__ __forceinline__ void fma2(u64& acc, u64 a, u64 b) {
    asm("fma.rn.f32x2 %0,%1,%2,%0;" : "+l"(acc) : "l"(a), "l"(b));
}
__device__ __forceinline__ u64 mul2(u64 a, u64 b) {
    u64 r; asm("mul.rn.f32x2 %0,%1,%2;" : "=l"(r) : "l"(a), "l"(b)); return r;
}
__device__ __forceinline__ void cpa16(u32 dst, const void* src) {
    asm volatile("cp.async.ca.shared.global [%0], [%1], 16;" :: "r"(dst), "l"(src));
}
__device__ __forceinline__ void cpa_commit() { asm volatile("cp.async.commit_group;"); }
__device__ __forceinline__ void cpa_wait0()  { asm volatile("cp.async.wait_group 0;"); }

// ---------- scratch (no cudaMalloc allowed) ----------
__device__ float g_q [(size_t)M_ * H_];   // Q, pre-scaled by D^-0.5
__device__ float g_kT[(size_t)M_ * H_];   // K, transposed per 64-row tile: [tile][d][64]
__device__ float g_v [(size_t)M_ * H_];

// ============================================================================
// Kernel 1: fused QKV projection. BM=64, BN=192 (K|Q|V), BK=32.
// Double-buffered: W via cp.async, x via register staging.
// xs stored transposed + duplicated: xs[k][2r..2r+1] = (x[r][k], x[r][k])
// so the A operand is one LDS.64 broadcast already in fma2 form.
// ============================================================================
#define XS_STR 130
#define WS_STR 196
#define XS_SZ (32*XS_STR)
#define WS_SZ (32*WS_STR)

// W chunk: 3 heads x 32 rows x 64 cols = 1536 float4s; 256 threads x 6 cp.async.
__device__ __forceinline__ void load_w_chunk(
    float* wbuf, int k0, int tid,
    const float* Wk, const float* Wq, const float* Wv)
{
    #pragma unroll
    for (int t = 0; t < 2; t++) {
        int idx = tid + t * 256;          // 0..511
        int k = idx >> 4;                 // 0..31
        int c = (idx & 15) * 4;           // 0..60
        const float* srcK = &Wk[(size_t)(k0 + k) * H_ + c];
        const float* srcQ = &Wq[(size_t)(k0 + k) * H_ + c];
        const float* srcV = &Wv[(size_t)(k0 + k) * H_ + c];
        cpa16((u32)__cvta_generic_to_shared(&wbuf[k*WS_STR +       c]), srcK);
        cpa16((u32)__cvta_generic_to_shared(&wbuf[k*WS_STR +  64 + c]), srcQ);
        cpa16((u32)__cvta_generic_to_shared(&wbuf[k*WS_STR + 128 + c]), srcV);
    }
}

__device__ __forceinline__ void store_x_dup(float* xbuf, const float4 xr[2], int lr, int lc8)
{
    const float* v = (const float*)xr;   // 8 floats
    #pragma unroll
    for (int j = 0; j < 8; j++)
        *(float2*)&xbuf[(lc8 + j)*XS_STR + 2*lr] = make_float2(v[j], v[j]);
}

__global__ __launch_bounds__(256, 2) void qkv_kernel(
    const float* __restrict__ x,
    const float* __restrict__ Wk, const float* __restrict__ Wq, const float* __restrict__ Wv)
{
    extern __shared__ float smq[];
    float* xs = smq;                 // [2][32][XS_STR]
    float* ws = smq + 2*XS_SZ;       // [2][32][WS_STR]

    const int tid = threadIdx.x;
    const int ty = tid >> 5;         // warp: owns rows 8ty..8ty+7
    const int tx = tid & 31;         // col pair 2tx within each head
    const int r0 = blockIdx.x * 64;
    const int lr = tid >> 2, lc8 = (tid & 3) * 8;

    u64 acc[8][3];
    #pragma unroll
    for (int i = 0; i < 8; i++)
        #pragma unroll
        for (int j = 0; j < 3; j++) acc[i][j] = 0ull;

    // prologue: chunk 0
    float4 xr[2];
    xr[0] = *(const float4*)&x[(size_t)(r0+lr)*D_ + lc8];
    xr[1] = *(const float4*)&x[(size_t)(r0+lr)*D_ + lc8 + 4];
    load_w_chunk(ws, 0, tid, Wk, Wq, Wv);
    cpa_commit();
    store_x_dup(xs, xr, lr, lc8);
    cpa_wait0();
    __syncthreads();

    int cur = 0;
    for (int ch = 0; ch < 32; ch++) {
        if (ch < 31) {
            int k0 = (ch + 1) * 32;
            xr[0] = *(const float4*)&x[(size_t)(r0+lr)*D_ + k0 + lc8];
            xr[1] = *(const float4*)&x[(size_t)(r0+lr)*D_ + k0 + lc8 + 4];
            load_w_chunk(ws + (cur^1)*WS_SZ, k0, tid, Wk, Wq, Wv);
            cpa_commit();
        }
        const float* xb = xs + cur*XS_SZ;
        const float* wb = ws + cur*WS_SZ;
        #pragma unroll 8
        for (int kk = 0; kk < 32; kk++) {
            u64 b0 = *(const u64*)&wb[kk*WS_STR +       2*tx];
            u64 b1 = *(const u64*)&wb[kk*WS_STR +  64 + 2*tx];
            u64 b2 = *(const u64*)&wb[kk*WS_STR + 128 + 2*tx];
            #pragma unroll
            for (int i = 0; i < 8; i++) {
                u64 aa = *(const u64*)&xb[kk*XS_STR + 2*(8*ty + i)];
                fma2(acc[i][0], aa, b0);
                fma2(acc[i][1], aa, b1);
                fma2(acc[i][2], aa, b2);
            }
        }
        if (ch < 31) {
            store_x_dup(xs + (cur^1)*XS_SZ, xr, lr, lc8);
            cpa_wait0();
            __syncthreads();
            cur ^= 1;
        }
    }

    // epilogue: K transposed per tile, Q scaled, V plain
    float* kt = g_kT + (size_t)blockIdx.x * (64*64);
    const float qs = 0.03125f;       // 1024^-0.5 (reference scales by embed dim)
    #pragma unroll
    for (int i = 0; i < 8; i++) {
        int rl = 8*ty + i;
        size_t row = (size_t)r0 + rl;
        float2 fk = unpack2(acc[i][0]);
        float2 fq = unpack2(acc[i][1]);
        float2 fv = unpack2(acc[i][2]);
        kt[(2*tx)  *64 + rl] = fk.x;
        kt[(2*tx+1)*64 + rl] = fk.y;
        *(float2*)&g_q[row*H_ + 2*tx] = make_float2(fq.x*qs, fq.y*qs);
        *(float2*)&g_v[row*H_ + 2*tx] = fv;
    }
}

// ============================================================================
// Kernel 2: paired flash attention, fp32 f32x2.
// CTA p handles q-tiles {p, 31-p}: uniform 33 tile-units, shared K/V loads.
// A operands (Q, P) in duplicated layout -> LDS.64 broadcast gives (a,a).
// Softmax in registers via half-warp shuffles (row = 16 consecutive lanes).
// ============================================================================
#define DP 132    // duplicated row stride (floats) = 2*64 + 4
#define KP 68     // K/V row stride

__device__ __forceinline__ void mm_dup(const float* __restrict__ Ad,
                                       const float* __restrict__ Bt,
                                       int ty4, int tx, u64 acc[4][2])
{
    #pragma unroll 8
    for (int d = 0; d < 64; d += 2) {
        ulonglong2 b0 = *(const ulonglong2*)&Bt[ d     *KP + tx*4];
        ulonglong2 b1 = *(const ulonglong2*)&Bt[(d + 1)*KP + tx*4];
        #pragma unroll
        for (int qi = 0; qi < 4; qi++) {
            ulonglong2 a01 = *(const ulonglong2*)&Ad[(ty4+qi)*DP + 2*d];
            fma2(acc[qi][0], a01.x, b0.x);
            fma2(acc[qi][1], a01.x, b0.y);
            fma2(acc[qi][0], a01.y, b1.x);
            fma2(acc[qi][1], a01.y, b1.y);
        }
    }
}

__device__ __forceinline__ void softmax_tile(
    u64 s2[4][2], float* msx, float* lsx, float alpha[4], float* Pxd,
    int ty4, int tx, bool diag)
{
    #pragma unroll
    for (int qi = 0; qi < 4; qi++) {
        float2 p0 = unpack2(s2[qi][0]);
        float2 p1 = unpack2(s2[qi][1]);
        if (diag) {
            int qg = ty4 + qi, kg = tx * 4;
            if (kg + 0 > qg) p0.x = -1e30f;
            if (kg + 1 > qg) p0.y = -1e30f;
            if (kg + 2 > qg) p1.x = -1e30f;
            if (kg + 3 > qg) p1.y = -1e30f;
        }
        float mx = fmaxf(fmaxf(p0.x, p0.y), fmaxf(p1.x, p1.y));
        #pragma unroll
        for (int m = 1; m < 16; m <<= 1)
            mx = fmaxf(mx, __shfl_xor_sync(0xffffffffu, mx, m));
        float mp = msx[ty4 + qi];
        float mn = fmaxf(mp, mx);
        float al = __expf(mp - mn);
        float e0 = __expf(p0.x - mn), e1 = __expf(p0.y - mn);
        float e2 = __expf(p1.x - mn), e3 = __expf(p1.y - mn);
        float sm = e0 + e1 + e2 + e3;
        #pragma unroll
        for (int m = 1; m < 16; m <<= 1)
            sm += __shfl_xor_sync(0xffffffffu, sm, m);
        if (tx == 0) { msx[ty4+qi] = mn; lsx[ty4+qi] = lsx[ty4+qi]*al + sm; }
        alpha[qi] = al;
        *(float4*)&Pxd[(ty4+qi)*DP + tx*8    ] = make_float4(e0, e0, e1, e1);
        *(float4*)&Pxd[(ty4+qi)*DP + tx*8 + 4] = make_float4(e2, e2, e3, e3);
    }
}

__global__ __launch_bounds__(256, 1) void attn_kernel(float* __restrict__ Out)
{
    extern __shared__ float sma[];
    float* Qad = sma;                  // [64][DP]
    float* Qbd = Qad + 64*DP;
    float* Pad = Qbd + 64*DP;
    float* Pbd = Pad + 64*DP;
    float* Ks  = Pbd + 64*DP;          // [64][KP]  rows=d, cols=k
    float* Vs  = Ks  + 64*KP;          // [64][KP]  rows=k, cols=h
    float* ma  = Vs  + 64*KP;
    float* la  = ma + 64;
    float* mb  = la + 64;
    float* lb  = mb + 64;

    const int tid = threadIdx.x;
    const int tx  = tid & 15;          // cols 4tx..4tx+3
    const int ty  = tid >> 4;          // rows 4ty..4ty+3
    const int ty4 = ty * 4;
    const int p   = blockIdx.x;        // 0..15
    const int b   = blockIdx.y;
    const int qa  = p, qb = 31 - p;

    const float* Qga = g_q + ((size_t)b*S_ + (size_t)qa*64) * H_;
    const float* Qgb = g_q + ((size_t)b*S_ + (size_t)qb*64) * H_;
    for (int i = tid; i < 1024; i += 256) {
        int r = i >> 4, c = (i & 15) * 4;
        float4 fa = *(const float4*)&Qga[(size_t)r*H_ + c];
        float4 fb = *(const float4*)&Qgb[(size_t)r*H_ + c];
        *(float4*)&Qad[r*DP + 2*c    ] = make_float4(fa.x, fa.x, fa.y, fa.y);
        *(float4*)&Qad[r*DP + 2*c + 4] = make_float4(fa.z, fa.z, fa.w, fa.w);
        *(float4*)&Qbd[r*DP + 2*c    ] = make_float4(fb.x, fb.x, fb.y, fb.y);
        *(float4*)&Qbd[r*DP + 2*c + 4] = make_float4(fb.z, fb.z, fb.w, fb.w);
    }
    if (tid < 64) { ma[tid] = -1e30f; la[tid] = 0.f; mb[tid] = -1e30f; lb[tid] = 0.f; }

    u64 oa[4][2], ob[4][2];
    #pragma unroll
    for (int qi = 0; qi < 4; qi++) {
        oa[qi][0] = oa[qi][1] = 0ull;
        ob[qi][0] = ob[qi][1] = 0ull;
    }

    const float* KTb = g_kT + (size_t)(b*32) * 4096;
    const float* Vgb = g_v  + (size_t)b * S_ * H_;

    for (int kt = 0; kt <= qb; kt++) {
        __syncthreads();               // prior PV done before K/V overwrite
        // batched loads -> regs -> smem (single exposed latency)
        const float* Kt = KTb + (size_t)kt * 4096;
        const float* Vt = Vgb + (size_t)kt * 64 * H_;
        float4 kreg[4], vreg[4];
        #pragma unroll
        for (int j = 0; j < 4; j++) {
            int i = tid + j*256;
            kreg[j] = *(const float4*)&Kt[i*4];
            vreg[j] = *(const float4*)&Vt[i*4];
        }
        #pragma unroll
        for (int j = 0; j < 4; j++) {
            int i = tid + j*256; int r = i >> 4, c = (i & 15) * 4;
            *(float4*)&Ks[r*KP + c] = kreg[j];
            *(float4*)&Vs[r*KP + c] = vreg[j];
        }
        __syncthreads();

        const bool act_a = (kt <= qa);
        float ala[4], alb[4];
        if (act_a) {
            u64 s2[4][2];
            #pragma unroll
            for (int qi = 0; qi < 4; qi++) { s2[qi][0] = 0ull; s2[qi][1] = 0ull; }
            mm_dup(Qad, Ks, ty4, tx, s2);
            softmax_tile(s2, ma, la, ala, Pad, ty4, tx, kt == qa);
        }
        {
            u64 s2[4][2];
            #pragma unroll
            for (int qi = 0; qi < 4; qi++) { s2[qi][0] = 0ull; s2[qi][1] = 0ull; }
            mm_dup(Qbd, Ks, ty4, tx, s2);
            softmax_tile(s2, mb, lb, alb, Pbd, ty4, tx, kt == qb);
        }
        __syncthreads();               // P visible

        if (act_a) {
            #pragma unroll
            for (int qi = 0; qi < 4; qi++) {
                u64 aa = pack2(ala[qi], ala[qi]);
                oa[qi][0] = mul2(oa[qi][0], aa);
                oa[qi][1] = mul2(oa[qi][1], aa);
            }
            mm_dup(Pad, Vs, ty4, tx, oa);
        }
        {
            #pragma unroll
            for (int qi = 0; qi < 4; qi++) {
                u64 aa = pack2(alb[qi], alb[qi]);
                ob[qi][0] = mul2(ob[qi][0], aa);
                ob[qi][1] = mul2(ob[qi][1], aa);
            }
            mm_dup(Pbd, Vs, ty4, tx, ob);
        }
    }

    __syncthreads();   // l-values (written by tx==0 lanes) visible to all lanes

    // write both q-tiles
    #pragma unroll
    for (int qi = 0; qi < 4; qi++) {
        {
            float inv = 1.0f / la[ty4 + qi];
            float2 p0 = unpack2(oa[qi][0]);
            float2 p1 = unpack2(oa[qi][1]);
            size_t row = (size_t)b*S_ + (size_t)qa*64 + ty4 + qi;
            *(float4*)&Out[row*H_ + tx*4] =
                make_float4(p0.x*inv, p0.y*inv, p1.x*inv, p1.y*inv);
        }
        {
            float inv = 1.0f / lb[ty4 + qi];
            float2 p0 = unpack2(ob[qi][0]);
            float2 p1 = unpack2(ob[qi][1]);
            size_t row = (size_t)b*S_ + (size_t)qb*64 + ty4 + qi;
            *(float4*)&Out[row*H_ + tx*4] =
                make_float4(p0.x*inv, p0.y*inv, p1.x*inv, p1.y*inv);
        }
    }
}

// ============================================================================
extern "C" void kernel_launch(void* const* d_in, const int* in_sizes, int n_in,
                              void* d_out, int out_size)
{
    const float* x  = (const float*)d_in[0];
    const float* Wk = (const float*)d_in[1];
    const float* Wq = (const float*)d_in[2];
    const float* Wv = (const float*)d_in[3];
    float* out = (float*)d_out;

    const int smem_qkv = (2*XS_SZ + 2*WS_SZ) * sizeof(float);            // 83456 B
    const int smem_att = (4*64*DP + 2*64*KP + 4*64) * sizeof(float);     // 171008 B
    cudaFuncSetAttribute(qkv_kernel, cudaFuncAttributeMaxDynamicSharedMemorySize, smem_qkv);
    cudaFuncSetAttribute(attn_kernel, cudaFuncAttributeMaxDynamicSharedMemorySize, smem_att);

    qkv_kernel<<<M_/64, 256, smem_qkv>>>(x, Wk, Wq, Wv);
    dim3 grid(16, B_);
    attn_kernel<<<grid, 256, smem_att>>>(out);
}

// round 5
// speedup vs baseline: 1.1788x; 1.0001x over previous
#include <cuda_runtime.h>
#include <cstdint>

#define B_ 8
#define S_ 2048
#define D_ 1024
#define H_ 64
#define M_ (B_*S_)      // 16384 rows

typedef unsigned long long u64;
typedef unsigned int u32;

// ---------- packed fp32x2 helpers ----------
__device__ __forceinline__ u64 pack2(float a, float b) {
    u64 r; asm("mov.b64 %0,{%1,%2};" : "=l"(r) : "f"(a), "f"(b)); return r;
}
__device__ __forceinline__ float2 unpack2(u64 v) {
    float2 r; asm("mov.b64 {%0,%1},%2;" : "=f"(r.x), "=f"(r.y) : "l"(v)); return r;
}
__device__ __forceinline__ void fma2(u64& acc, u64 a, u64 b) {
    asm("fma.rn.f32x2 %0,%1,%2,%0;" : "+l"(acc) : "l"(a), "l"(b));
}
__device__ __forceinline__ u64 mul2(u64 a, u64 b) {
    u64 r; asm("mul.rn.f32x2 %0,%1,%2;" : "=l"(r) : "l"(a), "l"(b)); return r;
}
__device__ __forceinline__ void cpa16(u32 dst, const void* src) {
    asm volatile("cp.async.ca.shared.global [%0], [%1], 16;" :: "r"(dst), "l"(src));
}
__device__ __forceinline__ void cpa_commit() { asm volatile("cp.async.commit_group;"); }
__device__ __forceinline__ void cpa_wait0()  { asm volatile("cp.async.wait_group 0;"); }

// ---------- scratch (no cudaMalloc allowed) ----------
__device__ float g_q [(size_t)M_ * H_];   // Q, pre-scaled by D^-0.5
__device__ float g_kT[(size_t)M_ * H_];   // K, transposed per 64-row tile: [tile][d][64]
__device__ float g_v [(size_t)M_ * H_];

// ============================================================================
// Kernel 1: fused QKV projection. BM=64, BN=192 (K|Q|V), BK=32.
// Double-buffered: W via cp.async, x via register staging.
// xs stored transposed + duplicated: xs[k][2r..2r+1] = (x[r][k], x[r][k])
// so the A operand is one LDS.64 broadcast already in fma2 form.
// ============================================================================
#define XS_STR 130
#define WS_STR 196
#define XS_SZ (32*XS_STR)
#define WS_SZ (32*WS_STR)

// W chunk: 3 heads x 32 rows x 64 cols = 1536 float4s; 256 threads x 6 cp.async.
__device__ __forceinline__ void load_w_chunk(
    float* wbuf, int k0, int tid,
    const float* Wk, const float* Wq, const float* Wv)
{
    #pragma unroll
    for (int t = 0; t < 2; t++) {
        int idx = tid + t * 256;          // 0..511
        int k = idx >> 4;                 // 0..31
        int c = (idx & 15) * 4;           // 0..60
        const float* srcK = &Wk[(size_t)(k0 + k) * H_ + c];
        const float* srcQ = &Wq[(size_t)(k0 + k) * H_ + c];
        const float* srcV = &Wv[(size_t)(k0 + k) * H_ + c];
        cpa16((u32)__cvta_generic_to_shared(&wbuf[k*WS_STR +       c]), srcK);
        cpa16((u32)__cvta_generic_to_shared(&wbuf[k*WS_STR +  64 + c]), srcQ);
        cpa16((u32)__cvta_generic_to_shared(&wbuf[k*WS_STR + 128 + c]), srcV);
    }
}

__device__ __forceinline__ void store_x_dup(float* xbuf, const float4 xr[2], int lr, int lc8)
{
    const float* v = (const float*)xr;   // 8 floats
    #pragma unroll
    for (int j = 0; j < 8; j++)
        *(float2*)&xbuf[(lc8 + j)*XS_STR + 2*lr] = make_float2(v[j], v[j]);
}

__global__ __launch_bounds__(256, 2) void qkv_kernel(
    const float* __restrict__ x,
    const float* __restrict__ Wk, const float* __restrict__ Wq, const float* __restrict__ Wv)
{
    extern __shared__ float smq[];
    float* xs = smq;                 // [2][32][XS_STR]
    float* ws = smq + 2*XS_SZ;       // [2][32][WS_STR]

    const int tid = threadIdx.x;
    const int ty = tid >> 5;         // warp: owns rows 8ty..8ty+7
    const int tx = tid & 31;         // col pair 2tx within each head
    const int r0 = blockIdx.x * 64;
    const int lr = tid >> 2, lc8 = (tid & 3) * 8;

    u64 acc[8][3];
    #pragma unroll
    for (int i = 0; i < 8; i++)
        #pragma unroll
        for (int j = 0; j < 3; j++) acc[i][j] = 0ull;

    // prologue: chunk 0
    float4 xr[2];
    xr[0] = *(const float4*)&x[(size_t)(r0+lr)*D_ + lc8];
    xr[1] = *(const float4*)&x[(size_t)(r0+lr)*D_ + lc8 + 4];
    load_w_chunk(ws, 0, tid, Wk, Wq, Wv);
    cpa_commit();
    store_x_dup(xs, xr, lr, lc8);
    cpa_wait0();
    __syncthreads();

    int cur = 0;
    for (int ch = 0; ch < 32; ch++) {
        if (ch < 31) {
            int k0 = (ch + 1) * 32;
            xr[0] = *(const float4*)&x[(size_t)(r0+lr)*D_ + k0 + lc8];
            xr[1] = *(const float4*)&x[(size_t)(r0+lr)*D_ + k0 + lc8 + 4];
            load_w_chunk(ws + (cur^1)*WS_SZ, k0, tid, Wk, Wq, Wv);
            cpa_commit();
        }
        const float* xb = xs + cur*XS_SZ;
        const float* wb = ws + cur*WS_SZ;
        #pragma unroll 8
        for (int kk = 0; kk < 32; kk++) {
            u64 b0 = *(const u64*)&wb[kk*WS_STR +       2*tx];
            u64 b1 = *(const u64*)&wb[kk*WS_STR +  64 + 2*tx];
            u64 b2 = *(const u64*)&wb[kk*WS_STR + 128 + 2*tx];
            #pragma unroll
            for (int i = 0; i < 8; i++) {
                u64 aa = *(const u64*)&xb[kk*XS_STR + 2*(8*ty + i)];
                fma2(acc[i][0], aa, b0);
                fma2(acc[i][1], aa, b1);
                fma2(acc[i][2], aa, b2);
            }
        }
        if (ch < 31) {
            store_x_dup(xs + (cur^1)*XS_SZ, xr, lr, lc8);
            cpa_wait0();
            __syncthreads();
            cur ^= 1;
        }
    }

    // epilogue: K transposed per tile, Q scaled, V plain
    float* kt = g_kT + (size_t)blockIdx.x * (64*64);
    const float qs = 0.03125f;       // 1024^-0.5 (reference scales by embed dim)
    #pragma unroll
    for (int i = 0; i < 8; i++) {
        int rl = 8*ty + i;
        size_t row = (size_t)r0 + rl;
        float2 fk = unpack2(acc[i][0]);
        float2 fq = unpack2(acc[i][1]);
        float2 fv = unpack2(acc[i][2]);
        kt[(2*tx)  *64 + rl] = fk.x;
        kt[(2*tx+1)*64 + rl] = fk.y;
        *(float2*)&g_q[row*H_ + 2*tx] = make_float2(fq.x*qs, fq.y*qs);
        *(float2*)&g_v[row*H_ + 2*tx] = fv;
    }
}

// ============================================================================
// Kernel 2: paired flash attention, fp32 f32x2.
// CTA p handles q-tiles {p, 31-p}: uniform 33 tile-units, shared K/V loads.
// A operands (Q, P) in duplicated layout -> LDS.64 broadcast gives (a,a).
// Softmax in registers via half-warp shuffles (row = 16 consecutive lanes).
// ============================================================================
#define DP 132    // duplicated row stride (floats) = 2*64 + 4
#define KP 68     // K/V row stride

__device__ __forceinline__ void mm_dup(const float* __restrict__ Ad,
                                       const float* __restrict__ Bt,
                                       int ty4, int tx, u64 acc[4][2])
{
    #pragma unroll 8
    for (int d = 0; d < 64; d += 2) {
        ulonglong2 b0 = *(const ulonglong2*)&Bt[ d     *KP + tx*4];
        ulonglong2 b1 = *(const ulonglong2*)&Bt[(d + 1)*KP + tx*4];
        #pragma unroll
        for (int qi = 0; qi < 4; qi++) {
            ulonglong2 a01 = *(const ulonglong2*)&Ad[(ty4+qi)*DP + 2*d];
            fma2(acc[qi][0], a01.x, b0.x);
            fma2(acc[qi][1], a01.x, b0.y);
            fma2(acc[qi][0], a01.y, b1.x);
            fma2(acc[qi][1], a01.y, b1.y);
        }
    }
}

__device__ __forceinline__ void softmax_tile(
    u64 s2[4][2], float* msx, float* lsx, float alpha[4], float* Pxd,
    int ty4, int tx, bool diag)
{
    #pragma unroll
    for (int qi = 0; qi < 4; qi++) {
        float2 p0 = unpack2(s2[qi][0]);
        float2 p1 = unpack2(s2[qi][1]);
        if (diag) {
            int qg = ty4 + qi, kg = tx * 4;
            if (kg + 0 > qg) p0.x = -1e30f;
            if (kg + 1 > qg) p0.y = -1e30f;
            if (kg + 2 > qg) p1.x = -1e30f;
            if (kg + 3 > qg) p1.y = -1e30f;
        }
        float mx = fmaxf(fmaxf(p0.x, p0.y), fmaxf(p1.x, p1.y));
        #pragma unroll
        for (int m = 1; m < 16; m <<= 1)
            mx = fmaxf(mx, __shfl_xor_sync(0xffffffffu, mx, m));
        float mp = msx[ty4 + qi];
        float mn = fmaxf(mp, mx);
        float al = __expf(mp - mn);
        float e0 = __expf(p0.x - mn), e1 = __expf(p0.y - mn);
        float e2 = __expf(p1.x - mn), e3 = __expf(p1.y - mn);
        float sm = e0 + e1 + e2 + e3;
        #pragma unroll
        for (int m = 1; m < 16; m <<= 1)
            sm += __shfl_xor_sync(0xffffffffu, sm, m);
        if (tx == 0) { msx[ty4+qi] = mn; lsx[ty4+qi] = lsx[ty4+qi]*al + sm; }
        alpha[qi] = al;
        *(float4*)&Pxd[(ty4+qi)*DP + tx*8    ] = make_float4(e0, e0, e1, e1);
        *(float4*)&Pxd[(ty4+qi)*DP + tx*8 + 4] = make_float4(e2, e2, e3, e3);
    }
}

__global__ __launch_bounds__(256, 1) void attn_kernel(float* __restrict__ Out)
{
    extern __shared__ float sma[];
    float* Qad = sma;                  // [64][DP]
    float* Qbd = Qad + 64*DP;
    float* Pad = Qbd + 64*DP;
    float* Pbd = Pad + 64*DP;
    float* Ks  = Pbd + 64*DP;          // [64][KP]  rows=d, cols=k
    float* Vs  = Ks  + 64*KP;          // [64][KP]  rows=k, cols=h
    float* ma  = Vs  + 64*KP;
    float* la  = ma + 64;
    float* mb  = la + 64;
    float* lb  = mb + 64;

    const int tid = threadIdx.x;
    const int tx  = tid & 15;          // cols 4tx..4tx+3
    const int ty  = tid >> 4;          // rows 4ty..4ty+3
    const int ty4 = ty * 4;
    const int p   = blockIdx.x;        // 0..15
    const int b   = blockIdx.y;
    const int qa  = p, qb = 31 - p;

    const float* Qga = g_q + ((size_t)b*S_ + (size_t)qa*64) * H_;
    const float* Qgb = g_q + ((size_t)b*S_ + (size_t)qb*64) * H_;
    for (int i = tid; i < 1024; i += 256) {
        int r = i >> 4, c = (i & 15) * 4;
        float4 fa = *(const float4*)&Qga[(size_t)r*H_ + c];
        float4 fb = *(const float4*)&Qgb[(size_t)r*H_ + c];
        *(float4*)&Qad[r*DP + 2*c    ] = make_float4(fa.x, fa.x, fa.y, fa.y);
        *(float4*)&Qad[r*DP + 2*c + 4] = make_float4(fa.z, fa.z, fa.w, fa.w);
        *(float4*)&Qbd[r*DP + 2*c    ] = make_float4(fb.x, fb.x, fb.y, fb.y);
        *(float4*)&Qbd[r*DP + 2*c + 4] = make_float4(fb.z, fb.z, fb.w, fb.w);
    }
    if (tid < 64) { ma[tid] = -1e30f; la[tid] = 0.f; mb[tid] = -1e30f; lb[tid] = 0.f; }

    u64 oa[4][2], ob[4][2];
    #pragma unroll
    for (int qi = 0; qi < 4; qi++) {
        oa[qi][0] = oa[qi][1] = 0ull;
        ob[qi][0] = ob[qi][1] = 0ull;
    }

    const float* KTb = g_kT + (size_t)(b*32) * 4096;
    const float* Vgb = g_v  + (size_t)b * S_ * H_;

    for (int kt = 0; kt <= qb; kt++) {
        __syncthreads();               // prior PV done before K/V overwrite
        // batched loads -> regs -> smem (single exposed latency)
        const float* Kt = KTb + (size_t)kt * 4096;
        const float* Vt = Vgb + (size_t)kt * 64 * H_;
        float4 kreg[4], vreg[4];
        #pragma unroll
        for (int j = 0; j < 4; j++) {
            int i = tid + j*256;
            kreg[j] = *(const float4*)&Kt[i*4];
            vreg[j] = *(const float4*)&Vt[i*4];
        }
        #pragma unroll
        for (int j = 0; j < 4; j++) {
            int i = tid + j*256; int r = i >> 4, c = (i & 15) * 4;
            *(float4*)&Ks[r*KP + c] = kreg[j];
            *(float4*)&Vs[r*KP + c] = vreg[j];
        }
        __syncthreads();

        const bool act_a = (kt <= qa);
        float ala[4], alb[4];
        if (act_a) {
            u64 s2[4][2];
            #pragma unroll
            for (int qi = 0; qi < 4; qi++) { s2[qi][0] = 0ull; s2[qi][1] = 0ull; }
            mm_dup(Qad, Ks, ty4, tx, s2);
            softmax_tile(s2, ma, la, ala, Pad, ty4, tx, kt == qa);
        }
        {
            u64 s2[4][2];
            #pragma unroll
            for (int qi = 0; qi < 4; qi++) { s2[qi][0] = 0ull; s2[qi][1] = 0ull; }
            mm_dup(Qbd, Ks, ty4, tx, s2);
            softmax_tile(s2, mb, lb, alb, Pbd, ty4, tx, kt == qb);
        }
        __syncthreads();               // P visible

        if (act_a) {
            #pragma unroll
            for (int qi = 0; qi < 4; qi++) {
                u64 aa = pack2(ala[qi], ala[qi]);
                oa[qi][0] = mul2(oa[qi][0], aa);
                oa[qi][1] = mul2(oa[qi][1], aa);
            }
            mm_dup(Pad, Vs, ty4, tx, oa);
        }
        {
            #pragma unroll
            for (int qi = 0; qi < 4; qi++) {
                u64 aa = pack2(alb[qi], alb[qi]);
                ob[qi][0] = mul2(ob[qi][0], aa);
                ob[qi][1] = mul2(ob[qi][1], aa);
            }
            mm_dup(Pbd, Vs, ty4, tx, ob);
        }
    }

    __syncthreads();   // l-values (written by tx==0 lanes) visible to all lanes

    // write both q-tiles
    #pragma unroll
    for (int qi = 0; qi < 4; qi++) {
        {
            float inv = 1.0f / la[ty4 + qi];
            float2 p0 = unpack2(oa[qi][0]);
            float2 p1 = unpack2(oa[qi][1]);
            size_t row = (size_t)b*S_ + (size_t)qa*64 + ty4 + qi;
            *(float4*)&Out[row*H_ + tx*4] =
                make_float4(p0.x*inv, p0.y*inv, p1.x*inv, p1.y*inv);
        }
        {
            float inv = 1.0f / lb[ty4 + qi];
            float2 p0 = unpack2(ob[qi][0]);
            float2 p1 = unpack2(ob[qi][1]);
            size_t row = (size_t)b*S_ + (size_t)qb*64 + ty4 + qi;
            *(float4*)&Out[row*H_ + tx*4] =
                make_float4(p0.x*inv, p0.y*inv, p1.x*inv, p1.y*inv);
        }
    }
}

// ============================================================================
extern "C" void kernel_launch(void* const* d_in, const int* in_sizes, int n_in,
                              void* d_out, int out_size)
{
    const float* x  = (const float*)d_in[0];
    const float* Wk = (const float*)d_in[1];
    const float* Wq = (const float*)d_in[2];
    const float* Wv = (const float*)d_in[3];
    float* out = (float*)d_out;

    const int smem_qkv = (2*XS_SZ + 2*WS_SZ) * sizeof(float);            // 83456 B
    const int smem_att = (4*64*DP + 2*64*KP + 4*64) * sizeof(float);     // 171008 B
    cudaFuncSetAttribute(qkv_kernel, cudaFuncAttributeMaxDynamicSharedMemorySize, smem_qkv);
    cudaFuncSetAttribute(attn_kernel, cudaFuncAttributeMaxDynamicSharedMemorySize, smem_att);

    qkv_kernel<<<M_/64, 256, smem_qkv>>>(x, Wk, Wq, Wv);
    dim3 grid(16, B_);
    attn_kernel<<<grid, 256, smem_att>>>(out);
}

// round 9
// speedup vs baseline: 3.1441x; 2.6671x over previous
#include <cuda_runtime.h>
#include <cstdint>

#define B_ 8
#define S_ 2048
#define D_ 1024
#define H_ 64
#define M_ (B_*S_)      // 16384 rows

typedef unsigned long long u64;
typedef unsigned int u32;
typedef unsigned short u16;

// ---------------------------------------------------------------------------
// helpers
// ---------------------------------------------------------------------------
// pack two floats to bf16x2: e0 -> low half, e1 -> high half
__device__ __forceinline__ u32 bf2(float e0, float e1) {
    u32 r; asm("cvt.rn.bf16x2.f32 %0,%1,%2;" : "=r"(r) : "f"(e1), "f"(e0)); return r;
}
__device__ __forceinline__ float lo_f(u32 v) { return __uint_as_float(v << 16); }
__device__ __forceinline__ float hi_f(u32 v) { return __uint_as_float(v & 0xffff0000u); }
__device__ __forceinline__ u16 bfc(float v) {
    u16 r; asm("cvt.rn.bf16.f32 %0,%1;" : "=h"(r) : "f"(v)); return r;
}
__device__ __forceinline__ float bfc_f(u16 u) { return __uint_as_float(((u32)u) << 16); }

__device__ __forceinline__ void cpa16(u32 dst, const void* src) {
    asm volatile("cp.async.ca.shared.global [%0], [%1], 16;" :: "r"(dst), "l"(src));
}
__device__ __forceinline__ void cpa_commit() { asm volatile("cp.async.commit_group;"); }
__device__ __forceinline__ void cpa_wait0()  { asm volatile("cp.async.wait_group 0;"); }

__device__ __forceinline__ void ldsm4(u32* r, u32 addr) {
    asm volatile("ldmatrix.sync.aligned.m8n8.x4.shared.b16 {%0,%1,%2,%3},[%4];"
        : "=r"(r[0]), "=r"(r[1]), "=r"(r[2]), "=r"(r[3]) : "r"(addr));
}
__device__ __forceinline__ void ldsm2(u32& r0, u32& r1, u32 addr) {
    asm volatile("ldmatrix.sync.aligned.m8n8.x2.shared.b16 {%0,%1},[%2];"
        : "=r"(r0), "=r"(r1) : "r"(addr));
}
__device__ __forceinline__ void hmma(float* c, const u32* a, u32 b0, u32 b1) {
    asm volatile("mma.sync.aligned.m16n8k16.row.col.f32.bf16.bf16.f32 "
        "{%0,%1,%2,%3},{%4,%5,%6,%7},{%8,%9},{%0,%1,%2,%3};"
        : "+f"(c[0]), "+f"(c[1]), "+f"(c[2]), "+f"(c[3])
        : "r"(a[0]), "r"(a[1]), "r"(a[2]), "r"(a[3]), "r"(b0), "r"(b1));
}
// swizzled smem addr: 128B rows; row*128 + (cb ^ ((row&7)<<4))
__device__ __forceinline__ u32 swadr(u32 base, int row, int cb) {
    return base + (u32)row * 128 + (u32)(cb ^ ((row & 7) << 4));
}

// ---------------------------------------------------------------------------
// scratch (no cudaMalloc allowed) — all bf16 (u16)
// ---------------------------------------------------------------------------
__device__ u16 g_qh[(size_t)M_ * H_], g_ql[(size_t)M_ * H_];   // Q hi/lo, [row][h], scaled
__device__ u16 g_kh[(size_t)M_ * H_], g_kl[(size_t)M_ * H_];   // K hi/lo, [row][h]
__device__ u16 g_vth[(size_t)M_ * H_], g_vtl[(size_t)M_ * H_]; // V^T hi/lo, [b][h][key]
__device__ u16 g_wTh[3 * 64 * 1024], g_wTl[3 * 64 * 1024];     // W^T hi/lo, [o][h][d]

// ============================================================================
// Kernel 0: transpose + bf16-split W. grid (16 d-chunks, 3 matrices), 256 thr.
// ============================================================================
__global__ __launch_bounds__(256) void wsplit_kernel(
    const float* __restrict__ Wk, const float* __restrict__ Wq, const float* __restrict__ Wv)
{
    __shared__ float ws[64][68];   // stride 68 floats = 272B: float4 stays 16B-aligned
    const int d0 = blockIdx.x * 64;
    const int o  = blockIdx.y;
    const float* W = (o == 0) ? Wk : (o == 1) ? Wq : Wv;
    const int tid = threadIdx.x;

    {   // load 64 d-rows x 64 h cols
        int r = tid >> 2, c = (tid & 3) * 16;
        #pragma unroll
        for (int i = 0; i < 4; i++)
            *(float4*)&ws[r][c + 4*i] = *(const float4*)&W[(size_t)(d0 + r) * H_ + c + 4*i];
    }
    __syncthreads();
    {   // write wT[h][d0..d0+63] split hi/lo, 16 d per thread
        int h = tid >> 2, dg = (tid & 3) * 16;
        u32 hi[8], lo[8];
        #pragma unroll
        for (int p = 0; p < 8; p++) {
            float v0 = ws[dg + 2*p    ][h];
            float v1 = ws[dg + 2*p + 1][h];
            u32 hp = bf2(v0, v1);
            hi[p] = hp;
            lo[p] = bf2(v0 - lo_f(hp), v1 - hi_f(hp));
        }
        size_t off = (size_t)o * 65536 + (size_t)h * 1024 + d0 + dg;  // u16 index
        *(uint4*)&g_wTh[off]     = make_uint4(hi[0], hi[1], hi[2], hi[3]);
        *(uint4*)&g_wTh[off + 8] = make_uint4(hi[4], hi[5], hi[6], hi[7]);
        *(uint4*)&g_wTl[off]     = make_uint4(lo[0], lo[1], lo[2], lo[3]);
        *(uint4*)&g_wTl[off + 8] = make_uint4(lo[4], lo[5], lo[6], lo[7]);
    }
}

// ============================================================================
// Kernel 1: QKV projection via mma.sync (split-bf16).
// 128 CTAs x 128 rows. 8 warps: each m16 x n192. 16 K-chunks of 64.
// smem buffer: xh 16K | xl 16K | wh 24K | wl 24K = 80K, double buffered.
// ============================================================================
#define QBUF 81920
__global__ __launch_bounds__(256, 1) void qkv_mma(const float* __restrict__ x)
{
    extern __shared__ char sm[];
    u32 smb;
    asm("{ .reg .u64 t; cvta.to.shared.u64 t, %1; cvt.u32.u64 %0, t; }" : "=r"(smb) : "l"(sm));
    const int tid = threadIdx.x, lane = tid & 31, w = tid >> 5;
    const int xrow = tid >> 1, xcol = (tid & 1) * 32;
    const size_t rbase = (size_t)blockIdx.x * 128;

    float ac[24][4];
    #pragma unroll
    for (int n = 0; n < 24; n++) { ac[n][0]=ac[n][1]=ac[n][2]=ac[n][3]=0.f; }

    const float* xp = x + (rbase + xrow) * D_ + xcol;

    auto load_chunk = [&](int ch, int buf) {
        u32 bb = smb + (u32)buf * QBUF;
        float4 xv[8];
        #pragma unroll
        for (int i = 0; i < 8; i++) xv[i] = *(const float4*)(xp + ch * 64 + 4*i);
        #pragma unroll
        for (int i = 0; i < 8; i++) {
            float4 v = xv[i];
            u32 h01 = bf2(v.x, v.y), h23 = bf2(v.z, v.w);
            u32 l01 = bf2(v.x - lo_f(h01), v.y - hi_f(h01));
            u32 l23 = bf2(v.z - lo_f(h23), v.w - hi_f(h23));
            u32 ad = swadr(bb, xrow, (xcol + 4*i) * 2);
            asm volatile("st.shared.v2.b32 [%0],{%1,%2};" :: "r"(ad), "r"(h01), "r"(h23) : "memory");
            asm volatile("st.shared.v2.b32 [%0],{%1,%2};" :: "r"(ad + 16384), "r"(l01), "r"(l23) : "memory");
        }
        #pragma unroll
        for (int k = 0; k < 12; k++) {
            int split = (k >= 6);
            int idx = tid + (k - split * 6) * 256;     // 0..1535
            int n = idx >> 3, g = idx & 7;             // n 0..191, g 0..7
            const u16* src = (split ? g_wTl : g_wTh) + (size_t)n * 1024 + ch * 64 + g * 8;
            u32 dst = swadr(bb + 32768 + (u32)split * 24576, n, g * 16);
            cpa16(dst, src);
        }
        cpa_commit();
    };

    load_chunk(0, 0); cpa_wait0(); __syncthreads();
    int cur = 0;
    for (int ch = 0; ch < 16; ch++) {
        if (ch < 15) load_chunk(ch + 1, cur ^ 1);
        u32 bb = smb + (u32)cur * QBUF;
        #pragma unroll
        for (int kk = 0; kk < 4; kk++) {
            u32 ah[4], al[4];
            {
                int sub = lane >> 3;
                int r = 16 * w + (lane & 7) + ((sub & 1) << 3);
                u32 ad = swadr(bb, r, kk * 32 + ((sub & 2) << 3));
                ldsm4(ah, ad);
                ldsm4(al, ad + 16384);
            }
            #pragma unroll
            for (int n = 0; n < 24; n++) {
                int r = 8 * n + (lane & 7);
                u32 ad = swadr(bb + 32768, r, kk * 32 + ((lane & 8) << 1));
                u32 bh0, bh1, bl0, bl1;
                ldsm2(bh0, bh1, ad);
                ldsm2(bl0, bl1, ad + 24576);
                hmma(ac[n], ah, bh0, bh1);
                hmma(ac[n], ah, bl0, bl1);
                hmma(ac[n], al, bh0, bh1);
            }
        }
        if (ch < 15) { cpa_wait0(); __syncthreads(); cur ^= 1; }
    }

    // epilogue: split to bf16 hi/lo; Q scaled; V transposed
    const int g = lane >> 2, i2 = (lane & 3) * 2;
    const size_t r0 = rbase + 16 * w + g, r1 = r0 + 8;
    const int bt = (int)(r0 >> 11);
    const int key0 = (int)(r0 & 2047), key1 = key0 + 8;
    #pragma unroll
    for (int n = 0; n < 24; n++) {
        int o = n >> 3, col = 8 * (n & 7) + i2;
        float v0 = ac[n][0], v1 = ac[n][1], v2 = ac[n][2], v3 = ac[n][3];
        if (o == 1) { v0 *= 0.03125f; v1 *= 0.03125f; v2 *= 0.03125f; v3 *= 0.03125f; }
        u16 h0 = bfc(v0), h1 = bfc(v1), h2 = bfc(v2), h3 = bfc(v3);
        u16 e0 = bfc(v0 - bfc_f(h0)), e1 = bfc(v1 - bfc_f(h1));
        u16 e2 = bfc(v2 - bfc_f(h2)), e3 = bfc(v3 - bfc_f(h3));
        if (o < 2) {
            u16* dh = o ? g_qh : g_kh;
            u16* dl = o ? g_ql : g_kl;
            *(u32*)&dh[r0 * 64 + col] = (u32)h0 | ((u32)h1 << 16);
            *(u32*)&dh[r1 * 64 + col] = (u32)h2 | ((u32)h3 << 16);
            *(u32*)&dl[r0 * 64 + col] = (u32)e0 | ((u32)e1 << 16);
            *(u32*)&dl[r1 * 64 + col] = (u32)e2 | ((u32)e3 << 16);
        } else {
            size_t c0 = ((size_t)bt * 64 + col) * 2048, c1 = c0 + 2048;
            g_vth[c0 + key0] = h0; g_vth[c1 + key0] = h1;
            g_vth[c0 + key1] = h2; g_vth[c1 + key1] = h3;
            g_vtl[c0 + key0] = e0; g_vtl[c1 + key0] = e1;
            g_vtl[c0 + key1] = e2; g_vtl[c1 + key1] = e3;
        }
    }
}

// ============================================================================
// Kernel 2: flash attention via mma.sync (split-bf16).
// grid (16 pairs, 8 batches), 256 thr. Warps 0-3 -> tile qa, 4-7 -> tile qb,
// each warp m16 q-rows x 64 keys. K/V double-buffered. Softmax in registers.
// smem: Q 4x8K | buf0: KH KL VH VL 4x8K | buf1 4x8K  = 96K
// ============================================================================
#define ABUF 32768
__global__ __launch_bounds__(256, 1) void attn_mma(float* __restrict__ Out)
{
    extern __shared__ char sm[];
    u32 smb;
    asm("{ .reg .u64 t; cvta.to.shared.u64 t, %1; cvt.u32.u64 %0, t; }" : "=r"(smb) : "l"(sm));
    const int tid = threadIdx.x, lane = tid & 31, w = tid >> 5;
    const int tile = w >> 2, mrow = 16 * (w & 3);
    const int p = blockIdx.x, b = blockIdx.y;
    const int qa = p, qb = 31 - p;
    const int qown = tile ? qb : qa;

    auto loadKV = [&](int kt, int buf) {
        #pragma unroll
        for (int k = 0; k < 8; k++) {
            int idx = tid + k * 256;
            int t = idx >> 9, rem = idx & 511, r = rem >> 3, gc = rem & 7;
            const u16* src;
            if (t < 2) src = (t ? g_kl : g_kh) + ((size_t)(b * S_ + kt * 64 + r)) * 64 + gc * 8;
            else       src = ((t == 2) ? g_vth : g_vtl) + ((size_t)(b * 64 + r)) * 2048 + kt * 64 + gc * 8;
            u32 dst = swadr(smb + 32768 + (u32)buf * ABUF + (u32)t * 8192, r, gc * 16);
            cpa16(dst, src);
        }
    };

    {   // Q tiles (4 x 8K: qaH qaL qbH qbL) + KV(0)
        #pragma unroll
        for (int k = 0; k < 8; k++) {
            int idx = tid + k * 256;
            int t = idx >> 9, rem = idx & 511, r = rem >> 3, gc = rem & 7;
            int qt = (t >> 1) ? qb : qa;
            const u16* src = ((t & 1) ? g_ql : g_qh) + ((size_t)(b * S_ + qt * 64 + r)) * 64 + gc * 8;
            u32 dst = swadr(smb + (u32)t * 8192, r, gc * 16);
            cpa16(dst, src);
        }
        loadKV(0, 0);
        cpa_commit(); cpa_wait0(); __syncthreads();
    }

    // preload Q fragments (constant across kt)
    u32 qh[4][4], ql[4][4];
    {
        u32 qbase = smb + (u32)tile * 16384;
        #pragma unroll
        for (int kk = 0; kk < 4; kk++) {
            int sub = lane >> 3;
            int r = mrow + (lane & 7) + ((sub & 1) << 3);
            u32 ad = swadr(qbase, r, kk * 32 + ((sub & 2) << 3));
            ldsm4(qh[kk], ad);
            ldsm4(ql[kk], ad + 8192);
        }
    }

    float o[8][4];
    #pragma unroll
    for (int n = 0; n < 8; n++) { o[n][0]=o[n][1]=o[n][2]=o[n][3]=0.f; }
    float m0 = -1e30f, m1 = -1e30f, l0 = 0.f, l1 = 0.f;

    int cur = 0;
    for (int kt = 0; kt <= qb; kt++) {
        if (kt < qb) { loadKV(kt + 1, cur ^ 1); cpa_commit(); }
        if (kt <= qown) {
            float s[8][4];
            #pragma unroll
            for (int n = 0; n < 8; n++) { s[n][0]=s[n][1]=s[n][2]=s[n][3]=0.f; }
            u32 kb = smb + 32768 + (u32)cur * ABUF;
            #pragma unroll
            for (int kk = 0; kk < 4; kk++) {
                #pragma unroll
                for (int n = 0; n < 8; n++) {
                    int r = 8 * n + (lane & 7);
                    u32 ad = swadr(kb, r, kk * 32 + ((lane & 8) << 1));
                    u32 bh0, bh1, bl0, bl1;
                    ldsm2(bh0, bh1, ad);
                    ldsm2(bl0, bl1, ad + 8192);
                    hmma(s[n], qh[kk], bh0, bh1);
                    hmma(s[n], qh[kk], bl0, bl1);
                    hmma(s[n], ql[kk], bh0, bh1);
                }
            }
            if (kt == qown) {       // causal mask on the diagonal tile
                int r0 = mrow + (lane >> 2), r1 = r0 + 8;
                #pragma unroll
                for (int n = 0; n < 8; n++) {
                    int c = 8 * n + (lane & 3) * 2;
                    if (c     > r0) s[n][0] = -1e30f;
                    if (c + 1 > r0) s[n][1] = -1e30f;
                    if (c     > r1) s[n][2] = -1e30f;
                    if (c + 1 > r1) s[n][3] = -1e30f;
                }
            }
            // online softmax (rows r0 = lane/4, r1 = +8; quad = lanes sharing lane>>2)
            float mx0 = -1e30f, mx1 = -1e30f;
            #pragma unroll
            for (int n = 0; n < 8; n++) {
                mx0 = fmaxf(mx0, fmaxf(s[n][0], s[n][1]));
                mx1 = fmaxf(mx1, fmaxf(s[n][2], s[n][3]));
            }
            mx0 = fmaxf(mx0, __shfl_xor_sync(0xffffffffu, mx0, 1));
            mx0 = fmaxf(mx0, __shfl_xor_sync(0xffffffffu, mx0, 2));
            mx1 = fmaxf(mx1, __shfl_xor_sync(0xffffffffu, mx1, 1));
            mx1 = fmaxf(mx1, __shfl_xor_sync(0xffffffffu, mx1, 2));
            float mn0 = fmaxf(m0, mx0), mn1 = fmaxf(m1, mx1);
            float a0 = __expf(m0 - mn0), a1 = __expf(m1 - mn1);
            float s0 = 0.f, s1 = 0.f;
            #pragma unroll
            for (int n = 0; n < 8; n++) {
                s[n][0] = __expf(s[n][0] - mn0); s[n][1] = __expf(s[n][1] - mn0);
                s[n][2] = __expf(s[n][2] - mn1); s[n][3] = __expf(s[n][3] - mn1);
                s0 += s[n][0] + s[n][1];
                s1 += s[n][2] + s[n][3];
            }
            s0 += __shfl_xor_sync(0xffffffffu, s0, 1);
            s0 += __shfl_xor_sync(0xffffffffu, s0, 2);
            s1 += __shfl_xor_sync(0xffffffffu, s1, 1);
            s1 += __shfl_xor_sync(0xffffffffu, s1, 2);
            l0 = l0 * a0 + s0; l1 = l1 * a1 + s1;
            m0 = mn0; m1 = mn1;
            #pragma unroll
            for (int n = 0; n < 8; n++) {
                o[n][0] *= a0; o[n][1] *= a0;
                o[n][2] *= a1; o[n][3] *= a1;
            }
            // PV: P fragments reuse S accumulator layout
            u32 vb = kb + 16384;
            #pragma unroll
            for (int kk = 0; kk < 4; kk++) {
                u32 ph[4], pl[4];
                float* sA = s[2*kk]; float* sB = s[2*kk + 1];
                ph[0] = bf2(sA[0], sA[1]); ph[1] = bf2(sA[2], sA[3]);
                ph[2] = bf2(sB[0], sB[1]); ph[3] = bf2(sB[2], sB[3]);
                pl[0] = bf2(sA[0] - lo_f(ph[0]), sA[1] - hi_f(ph[0]));
                pl[1] = bf2(sA[2] - lo_f(ph[1]), sA[3] - hi_f(ph[1]));
                pl[2] = bf2(sB[0] - lo_f(ph[2]), sB[1] - hi_f(ph[2]));
                pl[3] = bf2(sB[2] - lo_f(ph[3]), sB[3] - hi_f(ph[3]));
                #pragma unroll
                for (int n = 0; n < 8; n++) {
                    int r = 8 * n + (lane & 7);
                    u32 ad = swadr(vb, r, kk * 32 + ((lane & 8) << 1));
                    u32 vh0, vh1, vl0, vl1;
                    ldsm2(vh0, vh1, ad);
                    ldsm2(vl0, vl1, ad + 8192);
                    hmma(o[n], ph, vh0, vh1);
                    hmma(o[n], ph, vl0, vl1);
                    hmma(o[n], pl, vh0, vh1);
                }
            }
        }
        cpa_wait0(); __syncthreads(); cur ^= 1;
    }

    // epilogue
    float i0 = 1.f / l0, i1 = 1.f / l1;
    size_t r0 = (size_t)b * S_ + (size_t)qown * 64 + mrow + (lane >> 2), r1 = r0 + 8;
    #pragma unroll
    for (int n = 0; n < 8; n++) {
        int c = 8 * n + (lane & 3) * 2;
        *(float2*)&Out[r0 * 64 + c] = make_float2(o[n][0] * i0, o[n][1] * i0);
        *(float2*)&Out[r1 * 64 + c] = make_float2(o[n][2] * i1, o[n][3] * i1);
    }
}

// ============================================================================
extern "C" void kernel_launch(void* const* d_in, const int* in_sizes, int n_in,
                              void* d_out, int out_size)
{
    const float* x  = (const float*)d_in[0];
    const float* Wk = (const float*)d_in[1];
    const float* Wq = (const float*)d_in[2];
    const float* Wv = (const float*)d_in[3];
    float* out = (float*)d_out;

    const int smem_qkv = 2 * QBUF;            // 163840
    const int smem_att = 32768 + 2 * ABUF;    // 98304
    cudaFuncSetAttribute(qkv_mma,  cudaFuncAttributeMaxDynamicSharedMemorySize, smem_qkv);
    cudaFuncSetAttribute(attn_mma, cudaFuncAttributeMaxDynamicSharedMemorySize, smem_att);

    wsplit_kernel<<<dim3(16, 3), 256>>>(Wk, Wq, Wv);
    qkv_mma<<<M_ / 128, 256, smem_qkv>>>(x);
    attn_mma<<<dim3(16, B_), 256, smem_att>>>(out);
}

// round 12
// speedup vs baseline: 3.2052x; 1.0195x over previous
#include <cuda_runtime.h>
#include <cstdint>

#define B_ 8
#define S_ 2048
#define D_ 1024
#define H_ 64
#define M_ (B_*S_)      // 16384 rows

typedef unsigned long long u64;
typedef unsigned int u32;
typedef unsigned short u16;

// ---------------------------------------------------------------------------
// helpers
// ---------------------------------------------------------------------------
__device__ __forceinline__ u32 bf2(float e0, float e1) {
    u32 r; asm("cvt.rn.bf16x2.f32 %0,%1,%2;" : "=r"(r) : "f"(e1), "f"(e0)); return r;
}
__device__ __forceinline__ float lo_f(u32 v) { return __uint_as_float(v << 16); }
__device__ __forceinline__ float hi_f(u32 v) { return __uint_as_float(v & 0xffff0000u); }
__device__ __forceinline__ u16 bfc(float v) {
    u16 r; asm("cvt.rn.bf16.f32 %0,%1;" : "=h"(r) : "f"(v)); return r;
}
__device__ __forceinline__ float bfc_f(u16 u) { return __uint_as_float(((u32)u) << 16); }
__device__ __forceinline__ float ex2(float x) {
    float r; asm("ex2.approx.ftz.f32 %0,%1;" : "=f"(r) : "f"(x)); return r;
}

__device__ __forceinline__ void cpa16(u32 dst, const void* src) {
    asm volatile("cp.async.ca.shared.global [%0], [%1], 16;" :: "r"(dst), "l"(src));
}
__device__ __forceinline__ void cpa_commit() { asm volatile("cp.async.commit_group;"); }
__device__ __forceinline__ void cpa_wait0()  { asm volatile("cp.async.wait_group 0;"); }

__device__ __forceinline__ void ldsm4(u32* r, u32 addr) {
    asm volatile("ldmatrix.sync.aligned.m8n8.x4.shared.b16 {%0,%1,%2,%3},[%4];"
        : "=r"(r[0]), "=r"(r[1]), "=r"(r[2]), "=r"(r[3]) : "r"(addr));
}
__device__ __forceinline__ void hmma(float* c, const u32* a, u32 b0, u32 b1) {
    asm volatile("mma.sync.aligned.m16n8k16.row.col.f32.bf16.bf16.f32 "
        "{%0,%1,%2,%3},{%4,%5,%6,%7},{%8,%9},{%0,%1,%2,%3};"
        : "+f"(c[0]), "+f"(c[1]), "+f"(c[2]), "+f"(c[3])
        : "r"(a[0]), "r"(a[1]), "r"(a[2]), "r"(a[3]), "r"(b0), "r"(b1));
}
// swizzled smem addr: 128B rows; row*128 + (cb ^ ((row&7)<<4))
__device__ __forceinline__ u32 swadr(u32 base, int row, int cb) {
    return base + (u32)row * 128 + (u32)(cb ^ ((row & 7) << 4));
}

// ---------------------------------------------------------------------------
// scratch (no cudaMalloc allowed) — all bf16 (u16)
// ---------------------------------------------------------------------------
__device__ u16 g_qh[(size_t)M_ * H_], g_ql[(size_t)M_ * H_];   // Q hi/lo, [row][h], scaled
__device__ u16 g_kh[(size_t)M_ * H_], g_kl[(size_t)M_ * H_];   // K hi/lo, [row][h]
__device__ u16 g_vth[(size_t)M_ * H_], g_vtl[(size_t)M_ * H_]; // V^T hi/lo, [b][h][key]
__device__ u16 g_wTh[3 * 64 * 1024], g_wTl[3 * 64 * 1024];     // W^T hi/lo, [o][h][d]

// ============================================================================
// Kernel 0: transpose + bf16-split W. grid (16 d-chunks, 3 matrices), 256 thr.
// ============================================================================
__global__ __launch_bounds__(256) void wsplit_kernel(
    const float* __restrict__ Wk, const float* __restrict__ Wq, const float* __restrict__ Wv)
{
    __shared__ float ws[64][68];   // stride 68 floats = 272B: float4 stays 16B-aligned
    const int d0 = blockIdx.x * 64;
    const int o  = blockIdx.y;
    const float* W = (o == 0) ? Wk : (o == 1) ? Wq : Wv;
    const int tid = threadIdx.x;

    {   // load 64 d-rows x 64 h cols
        int r = tid >> 2, c = (tid & 3) * 16;
        #pragma unroll
        for (int i = 0; i < 4; i++)
            *(float4*)&ws[r][c + 4*i] = *(const float4*)&W[(size_t)(d0 + r) * H_ + c + 4*i];
    }
    __syncthreads();
    {   // write wT[h][d0..d0+63] split hi/lo, 16 d per thread
        int h = tid >> 2, dg = (tid & 3) * 16;
        u32 hi[8], lo[8];
        #pragma unroll
        for (int p = 0; p < 8; p++) {
            float v0 = ws[dg + 2*p    ][h];
            float v1 = ws[dg + 2*p + 1][h];
            u32 hp = bf2(v0, v1);
            hi[p] = hp;
            lo[p] = bf2(v0 - lo_f(hp), v1 - hi_f(hp));
        }
        size_t off = (size_t)o * 65536 + (size_t)h * 1024 + d0 + dg;  // u16 index
        *(uint4*)&g_wTh[off]     = make_uint4(hi[0], hi[1], hi[2], hi[3]);
        *(uint4*)&g_wTh[off + 8] = make_uint4(hi[4], hi[5], hi[6], hi[7]);
        *(uint4*)&g_wTl[off]     = make_uint4(lo[0], lo[1], lo[2], lo[3]);
        *(uint4*)&g_wTl[off + 8] = make_uint4(lo[4], lo[5], lo[6], lo[7]);
    }
}

// ============================================================================
// Kernel 1: QKV projection via mma.sync (split-bf16).
// 128 CTAs x 128 rows. 8 warps: each m16 x n192. 16 K-chunks of 64.
// smem buffer: xh 16K | xl 16K | wh 24K | wl 24K = 80K, double buffered.
// B fragments via ldsm4 (adjacent n-tile pairs).
// ============================================================================
#define QBUF 81920
__global__ __launch_bounds__(256, 1) void qkv_mma(const float* __restrict__ x)
{
    extern __shared__ char sm[];
    u32 smb;
    asm("{ .reg .u64 t; cvta.to.shared.u64 t, %1; cvt.u32.u64 %0, t; }" : "=r"(smb) : "l"(sm));
    const int tid = threadIdx.x, lane = tid & 31, w = tid >> 5;
    const int xrow = tid >> 1, xcol = (tid & 1) * 32;
    const size_t rbase = (size_t)blockIdx.x * 128;

    float ac[24][4];
    #pragma unroll
    for (int n = 0; n < 24; n++) { ac[n][0]=ac[n][1]=ac[n][2]=ac[n][3]=0.f; }

    const float* xp = x + (rbase + xrow) * D_ + xcol;

    auto load_chunk = [&](int ch, int buf) {
        u32 bb = smb + (u32)buf * QBUF;
        float4 xv[8];
        #pragma unroll
        for (int i = 0; i < 8; i++) xv[i] = *(const float4*)(xp + ch * 64 + 4*i);
        #pragma unroll
        for (int i = 0; i < 8; i++) {
            float4 v = xv[i];
            u32 h01 = bf2(v.x, v.y), h23 = bf2(v.z, v.w);
            u32 l01 = bf2(v.x - lo_f(h01), v.y - hi_f(h01));
            u32 l23 = bf2(v.z - lo_f(h23), v.w - hi_f(h23));
            u32 ad = swadr(bb, xrow, (xcol + 4*i) * 2);
            asm volatile("st.shared.v2.b32 [%0],{%1,%2};" :: "r"(ad), "r"(h01), "r"(h23) : "memory");
            asm volatile("st.shared.v2.b32 [%0],{%1,%2};" :: "r"(ad + 16384), "r"(l01), "r"(l23) : "memory");
        }
        #pragma unroll
        for (int k = 0; k < 12; k++) {
            int split = (k >= 6);
            int idx = tid + (k - split * 6) * 256;     // 0..1535
            int n = idx >> 3, g = idx & 7;             // n 0..191, g 0..7
            const u16* src = (split ? g_wTl : g_wTh) + (size_t)n * 1024 + ch * 64 + g * 8;
            u32 dst = swadr(bb + 32768 + (u32)split * 24576, n, g * 16);
            cpa16(dst, src);
        }
        cpa_commit();
    };

    load_chunk(0, 0); cpa_wait0(); __syncthreads();
    int cur = 0;
    // B ldsm4 lane map: pair (2np, 2np+1); row = 16np + 8*(lane>>4) + (lane&7)
    const int brow_off = 8 * (lane >> 4) + (lane & 7);
    const int bcol_off = ((lane >> 3) & 1) * 16;
    for (int ch = 0; ch < 16; ch++) {
        if (ch < 15) load_chunk(ch + 1, cur ^ 1);
        u32 bb = smb + (u32)cur * QBUF;
        #pragma unroll
        for (int kk = 0; kk < 4; kk++) {
            u32 ah[4], al[4];
            {
                int sub = lane >> 3;
                int r = 16 * w + (lane & 7) + ((sub & 1) << 3);
                u32 ad = swadr(bb, r, kk * 32 + ((sub & 2) << 3));
                ldsm4(ah, ad);
                ldsm4(al, ad + 16384);
            }
            #pragma unroll
            for (int np = 0; np < 12; np++) {
                int r = 16 * np + brow_off;
                u32 ad = swadr(bb + 32768, r, kk * 32 + bcol_off);
                u32 bh[4], bl[4];
                ldsm4(bh, ad);
                ldsm4(bl, ad + 24576);
                hmma(ac[2*np  ], ah, bh[0], bh[1]);
                hmma(ac[2*np  ], ah, bl[0], bl[1]);
                hmma(ac[2*np  ], al, bh[0], bh[1]);
                hmma(ac[2*np+1], ah, bh[2], bh[3]);
                hmma(ac[2*np+1], ah, bl[2], bl[3]);
                hmma(ac[2*np+1], al, bh[2], bh[3]);
            }
        }
        if (ch < 15) { cpa_wait0(); __syncthreads(); cur ^= 1; }
    }

    // epilogue: split to bf16 hi/lo; Q scaled (incl. log2e for base-2 softmax);
    // V transposed
    const int g = lane >> 2, i2 = (lane & 3) * 2;
    const size_t r0 = rbase + 16 * w + g, r1 = r0 + 8;
    const int bt = (int)(r0 >> 11);
    const int key0 = (int)(r0 & 2047), key1 = key0 + 8;
    const float QSC = 0.03125f * 1.4426950408889634f;   // D^-0.5 * log2(e)
    #pragma unroll
    for (int n = 0; n < 24; n++) {
        int o = n >> 3, col = 8 * (n & 7) + i2;
        float v0 = ac[n][0], v1 = ac[n][1], v2 = ac[n][2], v3 = ac[n][3];
        if (o == 1) { v0 *= QSC; v1 *= QSC; v2 *= QSC; v3 *= QSC; }
        u16 h0 = bfc(v0), h1 = bfc(v1), h2 = bfc(v2), h3 = bfc(v3);
        u16 e0 = bfc(v0 - bfc_f(h0)), e1 = bfc(v1 - bfc_f(h1));
        u16 e2 = bfc(v2 - bfc_f(h2)), e3 = bfc(v3 - bfc_f(h3));
        if (o < 2) {
            u16* dh = o ? g_qh : g_kh;
            u16* dl = o ? g_ql : g_kl;
            *(u32*)&dh[r0 * 64 + col] = (u32)h0 | ((u32)h1 << 16);
            *(u32*)&dh[r1 * 64 + col] = (u32)h2 | ((u32)h3 << 16);
            *(u32*)&dl[r0 * 64 + col] = (u32)e0 | ((u32)e1 << 16);
            *(u32*)&dl[r1 * 64 + col] = (u32)e2 | ((u32)e3 << 16);
        } else {
            size_t c0 = ((size_t)bt * 64 + col) * 2048, c1 = c0 + 2048;
            g_vth[c0 + key0] = h0; g_vth[c1 + key0] = h1;
            g_vth[c0 + key1] = h2; g_vth[c1 + key1] = h3;
            g_vtl[c0 + key0] = e0; g_vtl[c1 + key0] = e1;
            g_vtl[c0 + key1] = e2; g_vtl[c1 + key1] = e3;
        }
    }
}

// ============================================================================
// Kernel 2: flash attention via mma.sync (split-bf16, base-2 softmax).
// grid (16 pairs, 8 batches), 256 thr. Warps 0-3 -> tile qa, 4-7 -> tile qb.
// B fragments (K, V) via ldsm4 n-tile pairs. K/V double-buffered.
// smem: Q 4x8K | buf0: KH KL VH VL 4x8K | buf1 4x8K  = 96K
// ============================================================================
#define ABUF 32768
__global__ __launch_bounds__(256, 1) void attn_mma(float* __restrict__ Out)
{
    extern __shared__ char sm[];
    u32 smb;
    asm("{ .reg .u64 t; cvta.to.shared.u64 t, %1; cvt.u32.u64 %0, t; }" : "=r"(smb) : "l"(sm));
    const int tid = threadIdx.x, lane = tid & 31, w = tid >> 5;
    const int tile = w >> 2, mrow = 16 * (w & 3);
    const int p = blockIdx.x, b = blockIdx.y;
    const int qa = p, qb = 31 - p;
    const int qown = tile ? qb : qa;

    auto loadKV = [&](int kt, int buf) {
        #pragma unroll
        for (int k = 0; k < 8; k++) {
            int idx = tid + k * 256;
            int t = idx >> 9, rem = idx & 511, r = rem >> 3, gc = rem & 7;
            const u16* src;
            if (t < 2) src = (t ? g_kl : g_kh) + ((size_t)(b * S_ + kt * 64 + r)) * 64 + gc * 8;
            else       src = ((t == 2) ? g_vth : g_vtl) + ((size_t)(b * 64 + r)) * 2048 + kt * 64 + gc * 8;
            u32 dst = swadr(smb + 32768 + (u32)buf * ABUF + (u32)t * 8192, r, gc * 16);
            cpa16(dst, src);
        }
    };

    {   // Q tiles (4 x 8K: qaH qaL qbH qbL) + KV(0)
        #pragma unroll
        for (int k = 0; k < 8; k++) {
            int idx = tid + k * 256;
            int t = idx >> 9, rem = idx & 511, r = rem >> 3, gc = rem & 7;
            int qt = (t >> 1) ? qb : qa;
            const u16* src = ((t & 1) ? g_ql : g_qh) + ((size_t)(b * S_ + qt * 64 + r)) * 64 + gc * 8;
            u32 dst = swadr(smb + (u32)t * 8192, r, gc * 16);
            cpa16(dst, src);
        }
        loadKV(0, 0);
        cpa_commit(); cpa_wait0(); __syncthreads();
    }

    // preload Q fragments (constant across kt)
    u32 qh[4][4], ql[4][4];
    {
        u32 qbase = smb + (u32)tile * 16384;
        #pragma unroll
        for (int kk = 0; kk < 4; kk++) {
            int sub = lane >> 3;
            int r = mrow + (lane & 7) + ((sub & 1) << 3);
            u32 ad = swadr(qbase, r, kk * 32 + ((sub & 2) << 3));
            ldsm4(qh[kk], ad);
            ldsm4(ql[kk], ad + 8192);
        }
    }

    float o[8][4];
    #pragma unroll
    for (int n = 0; n < 8; n++) { o[n][0]=o[n][1]=o[n][2]=o[n][3]=0.f; }
    float m0 = -1e30f, m1 = -1e30f, l0 = 0.f, l1 = 0.f;

    const int brow_off = 8 * (lane >> 4) + (lane & 7);
    const int bcol_off = ((lane >> 3) & 1) * 16;

    int cur = 0;
    for (int kt = 0; kt <= qb; kt++) {
        if (kt < qb) { loadKV(kt + 1, cur ^ 1); cpa_commit(); }
        if (kt <= qown) {
            float s[8][4];
            #pragma unroll
            for (int n = 0; n < 8; n++) { s[n][0]=s[n][1]=s[n][2]=s[n][3]=0.f; }
            u32 kb = smb + 32768 + (u32)cur * ABUF;
            #pragma unroll
            for (int kk = 0; kk < 4; kk++) {
                #pragma unroll
                for (int np = 0; np < 4; np++) {
                    int r = 16 * np + brow_off;
                    u32 ad = swadr(kb, r, kk * 32 + bcol_off);
                    u32 bh[4], bl[4];
                    ldsm4(bh, ad);
                    ldsm4(bl, ad + 8192);
                    hmma(s[2*np  ], qh[kk], bh[0], bh[1]);
                    hmma(s[2*np  ], qh[kk], bl[0], bl[1]);
                    hmma(s[2*np  ], ql[kk], bh[0], bh[1]);
                    hmma(s[2*np+1], qh[kk], bh[2], bh[3]);
                    hmma(s[2*np+1], qh[kk], bl[2], bl[3]);
                    hmma(s[2*np+1], ql[kk], bh[2], bh[3]);
                }
            }
            if (kt == qown) {       // causal mask on the diagonal tile
                int r0 = mrow + (lane >> 2), r1 = r0 + 8;
                #pragma unroll
                for (int n = 0; n < 8; n++) {
                    int c = 8 * n + (lane & 3) * 2;
                    if (c     > r0) s[n][0] = -1e30f;
                    if (c + 1 > r0) s[n][1] = -1e30f;
                    if (c     > r1) s[n][2] = -1e30f;
                    if (c + 1 > r1) s[n][3] = -1e30f;
                }
            }
            // online softmax in base 2 (log2e folded into Q scale)
            float mx0 = -1e30f, mx1 = -1e30f;
            #pragma unroll
            for (int n = 0; n < 8; n++) {
                mx0 = fmaxf(mx0, fmaxf(s[n][0], s[n][1]));
                mx1 = fmaxf(mx1, fmaxf(s[n][2], s[n][3]));
            }
            mx0 = fmaxf(mx0, __shfl_xor_sync(0xffffffffu, mx0, 1));
            mx0 = fmaxf(mx0, __shfl_xor_sync(0xffffffffu, mx0, 2));
            mx1 = fmaxf(mx1, __shfl_xor_sync(0xffffffffu, mx1, 1));
            mx1 = fmaxf(mx1, __shfl_xor_sync(0xffffffffu, mx1, 2));
            float mn0 = fmaxf(m0, mx0), mn1 = fmaxf(m1, mx1);
            float a0 = ex2(m0 - mn0), a1 = ex2(m1 - mn1);
            float s0 = 0.f, s1 = 0.f;
            #pragma unroll
            for (int n = 0; n < 8; n++) {
                s[n][0] = ex2(s[n][0] - mn0); s[n][1] = ex2(s[n][1] - mn0);
                s[n][2] = ex2(s[n][2] - mn1); s[n][3] = ex2(s[n][3] - mn1);
                s0 += s[n][0] + s[n][1];
                s1 += s[n][2] + s[n][3];
            }
            s0 += __shfl_xor_sync(0xffffffffu, s0, 1);
            s0 += __shfl_xor_sync(0xffffffffu, s0, 2);
            s1 += __shfl_xor_sync(0xffffffffu, s1, 1);
            s1 += __shfl_xor_sync(0xffffffffu, s1, 2);
            l0 = l0 * a0 + s0; l1 = l1 * a1 + s1;
            m0 = mn0; m1 = mn1;
            #pragma unroll
            for (int n = 0; n < 8; n++) {
                o[n][0] *= a0; o[n][1] *= a0;
                o[n][2] *= a1; o[n][3] *= a1;
            }
            // PV: P fragments reuse S accumulator layout; V via ldsm4 pairs
            u32 vb = kb + 16384;
            #pragma unroll
            for (int kk = 0; kk < 4; kk++) {
                u32 ph[4], pl[4];
                float* sA = s[2*kk]; float* sB = s[2*kk + 1];
                ph[0] = bf2(sA[0], sA[1]); ph[1] = bf2(sA[2], sA[3]);
                ph[2] = bf2(sB[0], sB[1]); ph[3] = bf2(sB[2], sB[3]);
                pl[0] = bf2(sA[0] - lo_f(ph[0]), sA[1] - hi_f(ph[0]));
                pl[1] = bf2(sA[2] - lo_f(ph[1]), sA[3] - hi_f(ph[1]));
                pl[2] = bf2(sB[0] - lo_f(ph[2]), sB[1] - hi_f(ph[2]));
                pl[3] = bf2(sB[2] - lo_f(ph[3]), sB[3] - hi_f(ph[3]));
                #pragma unroll
                for (int np = 0; np < 4; np++) {
                    int r = 16 * np + brow_off;
                    u32 ad = swadr(vb, r, kk * 32 + bcol_off);
                    u32 vh[4], vl[4];
                    ldsm4(vh, ad);
                    ldsm4(vl, ad + 8192);
                    hmma(o[2*np  ], ph, vh[0], vh[1]);
                    hmma(o[2*np  ], ph, vl[0], vl[1]);
                    hmma(o[2*np  ], pl, vh[0], vh[1]);
                    hmma(o[2*np+1], ph, vh[2], vh[3]);
                    hmma(o[2*np+1], ph, vl[2], vl[3]);
                    hmma(o[2*np+1], pl, vh[2], vh[3]);
                }
            }
        }
        cpa_wait0(); __syncthreads(); cur ^= 1;
    }

    // epilogue
    float i0 = 1.f / l0, i1 = 1.f / l1;
    size_t r0 = (size_t)b * S_ + (size_t)qown * 64 + mrow + (lane >> 2), r1 = r0 + 8;
    #pragma unroll
    for (int n = 0; n < 8; n++) {
        int c = 8 * n + (lane & 3) * 2;
        *(float2*)&Out[r0 * 64 + c] = make_float2(o[n][0] * i0, o[n][1] * i0);
        *(float2*)&Out[r1 * 64 + c] = make_float2(o[n][2] * i1, o[n][3] * i1);
    }
}

// ============================================================================
extern "C" void kernel_launch(void* const* d_in, const int* in_sizes, int n_in,
                              void* d_out, int out_size)
{
    const float* x  = (const float*)d_in[0];
    const float* Wk = (const float*)d_in[1];
    const float* Wq = (const float*)d_in[2];
    const float* Wv = (const float*)d_in[3];
    float* out = (float*)d_out;

    const int smem_qkv = 2 * QBUF;            // 163840
    const int smem_att = 32768 + 2 * ABUF;    // 98304
    cudaFuncSetAttribute(qkv_mma,  cudaFuncAttributeMaxDynamicSharedMemorySize, smem_qkv);
    cudaFuncSetAttribute(attn_mma, cudaFuncAttributeMaxDynamicSharedMemorySize, smem_att);

    wsplit_kernel<<<dim3(16, 3), 256>>>(Wk, Wq, Wv);
    qkv_mma<<<M_ / 128, 256, smem_qkv>>>(x);
    attn_mma<<<dim3(16, B_), 256, smem_att>>>(out);
}

// round 13
// speedup vs baseline: 3.4943x; 1.0902x over previous
#include <cuda_runtime.h>
#include <cstdint>

#define B_ 8
#define S_ 2048
#define D_ 1024
#define H_ 64
#define M_ (B_*S_)      // 16384 rows

typedef unsigned long long u64;
typedef unsigned int u32;
typedef unsigned short u16;

// ---------------------------------------------------------------------------
// helpers
// ---------------------------------------------------------------------------
__device__ __forceinline__ u32 bf2(float e0, float e1) {
    u32 r; asm("cvt.rn.bf16x2.f32 %0,%1,%2;" : "=r"(r) : "f"(e1), "f"(e0)); return r;
}
__device__ __forceinline__ float lo_f(u32 v) { return __uint_as_float(v << 16); }
__device__ __forceinline__ float hi_f(u32 v) { return __uint_as_float(v & 0xffff0000u); }
__device__ __forceinline__ u16 bfc(float v) {
    u16 r; asm("cvt.rn.bf16.f32 %0,%1;" : "=h"(r) : "f"(v)); return r;
}
__device__ __forceinline__ float bfc_f(u16 u) { return __uint_as_float(((u32)u) << 16); }
__device__ __forceinline__ float ex2(float x) {
    float r; asm("ex2.approx.ftz.f32 %0,%1;" : "=f"(r) : "f"(x)); return r;
}

__device__ __forceinline__ void cpa16(u32 dst, const void* src) {
    asm volatile("cp.async.ca.shared.global [%0], [%1], 16;" :: "r"(dst), "l"(src));
}
__device__ __forceinline__ void cpa_commit() { asm volatile("cp.async.commit_group;"); }
__device__ __forceinline__ void cpa_wait0()  { asm volatile("cp.async.wait_group 0;"); }

__device__ __forceinline__ void ldsm4(u32* r, u32 addr) {
    asm volatile("ldmatrix.sync.aligned.m8n8.x4.shared.b16 {%0,%1,%2,%3},[%4];"
        : "=r"(r[0]), "=r"(r[1]), "=r"(r[2]), "=r"(r[3]) : "r"(addr));
}
__device__ __forceinline__ void hmma(float* c, const u32* a, u32 b0, u32 b1) {
    asm volatile("mma.sync.aligned.m16n8k16.row.col.f32.bf16.bf16.f32 "
        "{%0,%1,%2,%3},{%4,%5,%6,%7},{%8,%9},{%0,%1,%2,%3};"
        : "+f"(c[0]), "+f"(c[1]), "+f"(c[2]), "+f"(c[3])
        : "r"(a[0]), "r"(a[1]), "r"(a[2]), "r"(a[3]), "r"(b0), "r"(b1));
}
// swizzled smem addr: 128B rows; row*128 + (cb ^ ((row&7)<<4))
__device__ __forceinline__ u32 swadr(u32 base, int row, int cb) {
    return base + (u32)row * 128 + (u32)(cb ^ ((row & 7) << 4));
}

// ---------------------------------------------------------------------------
// scratch (no cudaMalloc allowed) — all bf16 (u16)
// ---------------------------------------------------------------------------
__device__ u16 g_qh[(size_t)M_ * H_], g_ql[(size_t)M_ * H_];   // Q hi/lo, [row][h], scaled
__device__ u16 g_kh[(size_t)M_ * H_], g_kl[(size_t)M_ * H_];   // K hi/lo, [row][h]
__device__ u16 g_vth[(size_t)M_ * H_], g_vtl[(size_t)M_ * H_]; // V^T hi/lo, [b][h][key]
__device__ u16 g_wTh[3 * 64 * 1024], g_wTl[3 * 64 * 1024];     // W^T hi/lo, [o][h][d]

// ============================================================================
// Kernel 0: transpose + bf16-split W. grid (16 d-chunks, 3 matrices), 256 thr.
// ============================================================================
__global__ __launch_bounds__(256) void wsplit_kernel(
    const float* __restrict__ Wk, const float* __restrict__ Wq, const float* __restrict__ Wv)
{
    __shared__ float ws[64][68];   // stride 68 floats = 272B: float4 stays 16B-aligned
    const int d0 = blockIdx.x * 64;
    const int o  = blockIdx.y;
    const float* W = (o == 0) ? Wk : (o == 1) ? Wq : Wv;
    const int tid = threadIdx.x;

    {   // load 64 d-rows x 64 h cols
        int r = tid >> 2, c = (tid & 3) * 16;
        #pragma unroll
        for (int i = 0; i < 4; i++)
            *(float4*)&ws[r][c + 4*i] = *(const float4*)&W[(size_t)(d0 + r) * H_ + c + 4*i];
    }
    __syncthreads();
    {   // write wT[h][d0..d0+63] split hi/lo, 16 d per thread
        int h = tid >> 2, dg = (tid & 3) * 16;
        u32 hi[8], lo[8];
        #pragma unroll
        for (int p = 0; p < 8; p++) {
            float v0 = ws[dg + 2*p    ][h];
            float v1 = ws[dg + 2*p + 1][h];
            u32 hp = bf2(v0, v1);
            hi[p] = hp;
            lo[p] = bf2(v0 - lo_f(hp), v1 - hi_f(hp));
        }
        size_t off = (size_t)o * 65536 + (size_t)h * 1024 + d0 + dg;  // u16 index
        *(uint4*)&g_wTh[off]     = make_uint4(hi[0], hi[1], hi[2], hi[3]);
        *(uint4*)&g_wTh[off + 8] = make_uint4(hi[4], hi[5], hi[6], hi[7]);
        *(uint4*)&g_wTl[off]     = make_uint4(lo[0], lo[1], lo[2], lo[3]);
        *(uint4*)&g_wTl[off + 8] = make_uint4(lo[4], lo[5], lo[6], lo[7]);
    }
}

// ============================================================================
// Kernel 1: QKV projection via mma.sync (split-bf16).
// 128 CTAs x 128 rows. 8 warps: each m16 x n192. 16 K-chunks of 64.
// x LDG + W cp.async for ch+1 issued BEFORE compute(ch): latency hidden.
// smem buffer: xh 16K | xl 16K | wh 24K | wl 24K = 80K, double buffered.
// ============================================================================
#define QBUF 81920
__global__ __launch_bounds__(256, 1) void qkv_mma(const float* __restrict__ x)
{
    extern __shared__ char sm[];
    u32 smb;
    asm("{ .reg .u64 t; cvta.to.shared.u64 t, %1; cvt.u32.u64 %0, t; }" : "=r"(smb) : "l"(sm));
    const int tid = threadIdx.x, lane = tid & 31, w = tid >> 5;
    const int xrow = tid >> 1, xcol = (tid & 1) * 32;
    const size_t rbase = (size_t)blockIdx.x * 128;

    float ac[24][4];
    #pragma unroll
    for (int n = 0; n < 24; n++) { ac[n][0]=ac[n][1]=ac[n][2]=ac[n][3]=0.f; }

    const float* xp = x + (rbase + xrow) * D_ + xcol;

    float4 xv[8];
    auto load_x = [&](int ch) {
        #pragma unroll
        for (int i = 0; i < 8; i++) xv[i] = *(const float4*)(xp + ch * 64 + 4*i);
    };
    auto issue_w = [&](int ch, u32 bb) {
        #pragma unroll
        for (int k = 0; k < 12; k++) {
            int split = (k >= 6);
            int idx = tid + (k - split * 6) * 256;     // 0..1535
            int n = idx >> 3, g = idx & 7;             // n 0..191, g 0..7
            const u16* src = (split ? g_wTl : g_wTh) + (size_t)n * 1024 + ch * 64 + g * 8;
            u32 dst = swadr(bb + 32768 + (u32)split * 24576, n, g * 16);
            cpa16(dst, src);
        }
        cpa_commit();
    };
    auto store_x = [&](u32 bb) {
        #pragma unroll
        for (int i = 0; i < 8; i++) {
            float4 v = xv[i];
            u32 h01 = bf2(v.x, v.y), h23 = bf2(v.z, v.w);
            u32 l01 = bf2(v.x - lo_f(h01), v.y - hi_f(h01));
            u32 l23 = bf2(v.z - lo_f(h23), v.w - hi_f(h23));
            u32 ad = swadr(bb, xrow, (xcol + 4*i) * 2);
            asm volatile("st.shared.v2.b32 [%0],{%1,%2};" :: "r"(ad), "r"(h01), "r"(h23) : "memory");
            asm volatile("st.shared.v2.b32 [%0],{%1,%2};" :: "r"(ad + 16384), "r"(l01), "r"(l23) : "memory");
        }
    };

    // prologue: chunk 0
    load_x(0); issue_w(0, smb); store_x(smb);
    cpa_wait0(); __syncthreads();

    int cur = 0;
    const int brow_off = 8 * (lane >> 4) + (lane & 7);
    const int bcol_off = ((lane >> 3) & 1) * 16;
    for (int ch = 0; ch < 16; ch++) {
        u32 nb = smb + (u32)(cur ^ 1) * QBUF;
        if (ch < 15) { load_x(ch + 1); issue_w(ch + 1, nb); }   // in flight during compute
        u32 bb = smb + (u32)cur * QBUF;
        #pragma unroll
        for (int kk = 0; kk < 4; kk++) {
            u32 ah[4], al[4];
            {
                int sub = lane >> 3;
                int r = 16 * w + (lane & 7) + ((sub & 1) << 3);
                u32 ad = swadr(bb, r, kk * 32 + ((sub & 2) << 3));
                ldsm4(ah, ad);
                ldsm4(al, ad + 16384);
            }
            #pragma unroll
            for (int np = 0; np < 12; np++) {
                int r = 16 * np + brow_off;
                u32 ad = swadr(bb + 32768, r, kk * 32 + bcol_off);
                u32 bh[4], bl[4];
                ldsm4(bh, ad);
                ldsm4(bl, ad + 24576);
                hmma(ac[2*np  ], ah, bh[0], bh[1]);
                hmma(ac[2*np  ], ah, bl[0], bl[1]);
                hmma(ac[2*np  ], al, bh[0], bh[1]);
                hmma(ac[2*np+1], ah, bh[2], bh[3]);
                hmma(ac[2*np+1], ah, bl[2], bl[3]);
                hmma(ac[2*np+1], al, bh[2], bh[3]);
            }
        }
        if (ch < 15) {
            store_x(nb);
            cpa_wait0(); __syncthreads();
            cur ^= 1;
        }
    }

    // epilogue: split to bf16 hi/lo; Q scaled (incl. log2e for base-2 softmax);
    // V transposed
    const int g = lane >> 2, i2 = (lane & 3) * 2;
    const size_t r0 = rbase + 16 * w + g, r1 = r0 + 8;
    const int bt = (int)(r0 >> 11);
    const int key0 = (int)(r0 & 2047), key1 = key0 + 8;
    const float QSC = 0.03125f * 1.4426950408889634f;   // D^-0.5 * log2(e)
    #pragma unroll
    for (int n = 0; n < 24; n++) {
        int o = n >> 3, col = 8 * (n & 7) + i2;
        float v0 = ac[n][0], v1 = ac[n][1], v2 = ac[n][2], v3 = ac[n][3];
        if (o == 1) { v0 *= QSC; v1 *= QSC; v2 *= QSC; v3 *= QSC; }
        u16 h0 = bfc(v0), h1 = bfc(v1), h2 = bfc(v2), h3 = bfc(v3);
        u16 e0 = bfc(v0 - bfc_f(h0)), e1 = bfc(v1 - bfc_f(h1));
        u16 e2 = bfc(v2 - bfc_f(h2)), e3 = bfc(v3 - bfc_f(h3));
        if (o < 2) {
            u16* dh = o ? g_qh : g_kh;
            u16* dl = o ? g_ql : g_kl;
            *(u32*)&dh[r0 * 64 + col] = (u32)h0 | ((u32)h1 << 16);
            *(u32*)&dh[r1 * 64 + col] = (u32)h2 | ((u32)h3 << 16);
            *(u32*)&dl[r0 * 64 + col] = (u32)e0 | ((u32)e1 << 16);
            *(u32*)&dl[r1 * 64 + col] = (u32)e2 | ((u32)e3 << 16);
        } else {
            size_t c0 = ((size_t)bt * 64 + col) * 2048, c1 = c0 + 2048;
            g_vth[c0 + key0] = h0; g_vth[c1 + key0] = h1;
            g_vth[c0 + key1] = h2; g_vth[c1 + key1] = h3;
            g_vtl[c0 + key0] = e0; g_vtl[c1 + key0] = e1;
            g_vtl[c0 + key1] = e2; g_vtl[c1 + key1] = e3;
        }
    }
}

// ============================================================================
// Kernel 2: flash attention, ONE q-tile per CTA (128 thr), 2 CTAs/SM.
// Grid 256 = all (qt, batch) jobs, sized descending; bids k and k+148 land on
// the same SM (classic LUT is bid%148) and their step counts sum ~constant.
// smem: Qh|Ql 16K | buf0: KH KL VH VL 32K | buf1 32K = 80K  -> 2 CTAs/SM.
// ============================================================================
#define ABUF 32768
__global__ __launch_bounds__(128, 2) void attn_mma(float* __restrict__ Out)
{
    extern __shared__ char sm[];
    u32 smb;
    asm("{ .reg .u64 t; cvta.to.shared.u64 t, %1; cvt.u32.u64 %0, t; }" : "=r"(smb) : "l"(sm));
    const int tid = threadIdx.x, lane = tid & 31, w = tid >> 5;
    const int mrow = 16 * w;
    const int bid = blockIdx.x;
    const int j   = (bid < 148) ? bid : 403 - bid;   // bijection 0..255, desc sizes first
    const int qt  = 31 - (j >> 3);
    const int b   = j & 7;

    auto loadKV = [&](int kt, int buf) {
        #pragma unroll
        for (int k = 0; k < 16; k++) {
            int idx = tid + k * 128;
            int t = idx >> 9, rem = idx & 511, r = rem >> 3, gc = rem & 7;
            const u16* src;
            if (t < 2) src = (t ? g_kl : g_kh) + ((size_t)(b * S_ + kt * 64 + r)) * 64 + gc * 8;
            else       src = ((t == 2) ? g_vth : g_vtl) + ((size_t)(b * 64 + r)) * 2048 + kt * 64 + gc * 8;
            u32 dst = swadr(smb + 16384 + (u32)buf * ABUF + (u32)t * 8192, r, gc * 16);
            cpa16(dst, src);
        }
    };

    {   // Q tile (Qh, Ql) + KV(0)
        #pragma unroll
        for (int k = 0; k < 8; k++) {
            int idx = tid + k * 128;
            int t = idx >> 9, rem = idx & 511, r = rem >> 3, gc = rem & 7;
            const u16* src = (t ? g_ql : g_qh) + ((size_t)(b * S_ + qt * 64 + r)) * 64 + gc * 8;
            u32 dst = swadr(smb + (u32)t * 8192, r, gc * 16);
            cpa16(dst, src);
        }
        loadKV(0, 0);
        cpa_commit(); cpa_wait0(); __syncthreads();
    }

    // preload Q fragments (constant across kt)
    u32 qh[4][4], ql[4][4];
    {
        #pragma unroll
        for (int kk = 0; kk < 4; kk++) {
            int sub = lane >> 3;
            int r = mrow + (lane & 7) + ((sub & 1) << 3);
            u32 ad = swadr(smb, r, kk * 32 + ((sub & 2) << 3));
            ldsm4(qh[kk], ad);
            ldsm4(ql[kk], ad + 8192);
        }
    }

    float o[8][4];
    #pragma unroll
    for (int n = 0; n < 8; n++) { o[n][0]=o[n][1]=o[n][2]=o[n][3]=0.f; }
    float m0 = -1e30f, m1 = -1e30f, l0 = 0.f, l1 = 0.f;

    const int brow_off = 8 * (lane >> 4) + (lane & 7);
    const int bcol_off = ((lane >> 3) & 1) * 16;

    int cur = 0;
    for (int kt = 0; kt <= qt; kt++) {
        if (kt < qt) { loadKV(kt + 1, cur ^ 1); cpa_commit(); }
        {
            float s[8][4];
            #pragma unroll
            for (int n = 0; n < 8; n++) { s[n][0]=s[n][1]=s[n][2]=s[n][3]=0.f; }
            u32 kb = smb + 16384 + (u32)cur * ABUF;
            #pragma unroll
            for (int kk = 0; kk < 4; kk++) {
                #pragma unroll
                for (int np = 0; np < 4; np++) {
                    int r = 16 * np + brow_off;
                    u32 ad = swadr(kb, r, kk * 32 + bcol_off);
                    u32 bh[4], bl[4];
                    ldsm4(bh, ad);
                    ldsm4(bl, ad + 8192);
                    hmma(s[2*np  ], qh[kk], bh[0], bh[1]);
                    hmma(s[2*np  ], qh[kk], bl[0], bl[1]);
                    hmma(s[2*np  ], ql[kk], bh[0], bh[1]);
                    hmma(s[2*np+1], qh[kk], bh[2], bh[3]);
                    hmma(s[2*np+1], qh[kk], bl[2], bl[3]);
                    hmma(s[2*np+1], ql[kk], bh[2], bh[3]);
                }
            }
            if (kt == qt) {        // causal mask on the diagonal tile
                int r0 = mrow + (lane >> 2), r1 = r0 + 8;
                #pragma unroll
                for (int n = 0; n < 8; n++) {
                    int c = 8 * n + (lane & 3) * 2;
                    if (c     > r0) s[n][0] = -1e30f;
                    if (c + 1 > r0) s[n][1] = -1e30f;
                    if (c     > r1) s[n][2] = -1e30f;
                    if (c + 1 > r1) s[n][3] = -1e30f;
                }
            }
            // online softmax in base 2 (log2e folded into Q scale)
            float mx0 = -1e30f, mx1 = -1e30f;
            #pragma unroll
            for (int n = 0; n < 8; n++) {
                mx0 = fmaxf(mx0, fmaxf(s[n][0], s[n][1]));
                mx1 = fmaxf(mx1, fmaxf(s[n][2], s[n][3]));
            }
            mx0 = fmaxf(mx0, __shfl_xor_sync(0xffffffffu, mx0, 1));
            mx0 = fmaxf(mx0, __shfl_xor_sync(0xffffffffu, mx0, 2));
            mx1 = fmaxf(mx1, __shfl_xor_sync(0xffffffffu, mx1, 1));
            mx1 = fmaxf(mx1, __shfl_xor_sync(0xffffffffu, mx1, 2));
            float mn0 = fmaxf(m0, mx0), mn1 = fmaxf(m1, mx1);
            float a0 = ex2(m0 - mn0), a1 = ex2(m1 - mn1);
            float s0 = 0.f, s1 = 0.f;
            #pragma unroll
            for (int n = 0; n < 8; n++) {
                s[n][0] = ex2(s[n][0] - mn0); s[n][1] = ex2(s[n][1] - mn0);
                s[n][2] = ex2(s[n][2] - mn1); s[n][3] = ex2(s[n][3] - mn1);
                s0 += s[n][0] + s[n][1];
                s1 += s[n][2] + s[n][3];
            }
            s0 += __shfl_xor_sync(0xffffffffu, s0, 1);
            s0 += __shfl_xor_sync(0xffffffffu, s0, 2);
            s1 += __shfl_xor_sync(0xffffffffu, s1, 1);
            s1 += __shfl_xor_sync(0xffffffffu, s1, 2);
            l0 = l0 * a0 + s0; l1 = l1 * a1 + s1;
            m0 = mn0; m1 = mn1;
            #pragma unroll
            for (int n = 0; n < 8; n++) {
                o[n][0] *= a0; o[n][1] *= a0;
                o[n][2] *= a1; o[n][3] *= a1;
            }
            // PV: P fragments reuse S accumulator layout; V via ldsm4 pairs
            u32 vb = kb + 16384;
            #pragma unroll
            for (int kk = 0; kk < 4; kk++) {
                u32 ph[4], pl[4];
                float* sA = s[2*kk]; float* sB = s[2*kk + 1];
                ph[0] = bf2(sA[0], sA[1]); ph[1] = bf2(sA[2], sA[3]);
                ph[2] = bf2(sB[0], sB[1]); ph[3] = bf2(sB[2], sB[3]);
                pl[0] = bf2(sA[0] - lo_f(ph[0]), sA[1] - hi_f(ph[0]));
                pl[1] = bf2(sA[2] - lo_f(ph[1]), sA[3] - hi_f(ph[1]));
                pl[2] = bf2(sB[0] - lo_f(ph[2]), sB[1] - hi_f(ph[2]));
                pl[3] = bf2(sB[2] - lo_f(ph[3]), sB[3] - hi_f(ph[3]));
                #pragma unroll
                for (int np = 0; np < 4; np++) {
                    int r = 16 * np + brow_off;
                    u32 ad = swadr(vb, r, kk * 32 + bcol_off);
                    u32 vh[4], vl[4];
                    ldsm4(vh, ad);
                    ldsm4(vl, ad + 8192);
                    hmma(o[2*np  ], ph, vh[0], vh[1]);
                    hmma(o[2*np  ], ph, vl[0], vl[1]);
                    hmma(o[2*np  ], pl, vh[0], vh[1]);
                    hmma(o[2*np+1], ph, vh[2], vh[3]);
                    hmma(o[2*np+1], ph, vl[2], vl[3]);
                    hmma(o[2*np+1], pl, vh[2], vh[3]);
                }
            }
        }
        cpa_wait0(); __syncthreads(); cur ^= 1;
    }

    // epilogue
    float i0 = 1.f / l0, i1 = 1.f / l1;
    size_t r0 = (size_t)b * S_ + (size_t)qt * 64 + mrow + (lane >> 2), r1 = r0 + 8;
    #pragma unroll
    for (int n = 0; n < 8; n++) {
        int c = 8 * n + (lane & 3) * 2;
        *(float2*)&Out[r0 * 64 + c] = make_float2(o[n][0] * i0, o[n][1] * i0);
        *(float2*)&Out[r1 * 64 + c] = make_float2(o[n][2] * i1, o[n][3] * i1);
    }
}

// ============================================================================
extern "C" void kernel_launch(void* const* d_in, const int* in_sizes, int n_in,
                              void* d_out, int out_size)
{
    const float* x  = (const float*)d_in[0];
    const float* Wk = (const float*)d_in[1];
    const float* Wq = (const float*)d_in[2];
    const float* Wv = (const float*)d_in[3];
    float* out = (float*)d_out;

    const int smem_qkv = 2 * QBUF;            // 163840
    const int smem_att = 16384 + 2 * ABUF;    // 81920 -> 2 CTAs/SM
    cudaFuncSetAttribute(qkv_mma,  cudaFuncAttributeMaxDynamicSharedMemorySize, smem_qkv);
    cudaFuncSetAttribute(attn_mma, cudaFuncAttributeMaxDynamicSharedMemorySize, smem_att);

    wsplit_kernel<<<dim3(16, 3), 256>>>(Wk, Wq, Wv);
    qkv_mma<<<M_ / 128, 256, smem_qkv>>>(x);
    attn_mma<<<256, 128, smem_att>>>(out);
}